// round 14
// baseline (speedup 1.0000x reference)
#include <cuda_runtime.h>
#include <cuda_bf16.h>
#include <math.h>
#include <stdint.h>

// ---------------- problem constants ----------------
#define BATCH 64
#define NPTS  1024
#define KCPL  256
#define NCLS  40
#define BN_EPS 1e-5f
#define CPL_EPS 1e-7f

// ---------------- device scratch ----------------
__device__ float g_y1[BATCH * 64 * NPTS];
__device__ float g_y2[BATCH * 128 * NPTS];
__device__ __nv_bfloat16 g_h3bh[BATCH * 128 * NPTS];
__device__ __nv_bfloat16 g_h3bl[BATCH * 128 * NPTS];
__device__ __nv_bfloat16 g_h2gh[BATCH * 128 * KCPL];
__device__ __nv_bfloat16 g_h2gl[BATCH * 128 * KCPL];
__device__ __nv_bfloat16 g_crith[(size_t)BATCH * 1024 * KCPL];
__device__ __nv_bfloat16 g_critl[(size_t)BATCH * 1024 * KCPL];
__device__ __nv_bfloat16 g_W3h[1024 * 128], g_W3l[1024 * 128];
__device__ __nv_bfloat16 g_Wch[1024 * 1024], g_Wcl[1024 * 1024];
__device__ float g_psum3[1024 * 1024];
__device__ float g_psq3[1024 * 1024];
__device__ float g_pmax[BATCH * 1024 * 16];
__device__ int   g_pamax[BATCH * 1024 * 16];
__device__ float g_pmin[BATCH * 1024 * 16];
__device__ int   g_pamin[BATCH * 1024 * 16];
__device__ float g_psumc[1024 * 256];
__device__ float g_psqc[1024 * 256];
__device__ float g_gfeat[BATCH * 1024];
__device__ float g_fc1h[BATCH * 512];
__device__ float g_fc2h[BATCH * 256];
__device__ int   g_cidx[BATCH * KCPL];
__device__ float g_bn[8 * 1024];

// ---------------- ptx helpers ----------------
__device__ __forceinline__ uint32_t smem_u32(const void* p) {
    return (uint32_t)__cvta_generic_to_shared(p);
}
__device__ __forceinline__ void ldsm_x4(uint32_t* r, uint32_t a) {
    asm volatile("ldmatrix.sync.aligned.m8n8.x4.shared.b16 {%0,%1,%2,%3}, [%4];"
        : "=r"(r[0]), "=r"(r[1]), "=r"(r[2]), "=r"(r[3]) : "r"(a));
}
__device__ __forceinline__ void ldsm_x4_t(uint32_t* r, uint32_t a) {
    asm volatile("ldmatrix.sync.aligned.m8n8.x4.trans.shared.b16 {%0,%1,%2,%3}, [%4];"
        : "=r"(r[0]), "=r"(r[1]), "=r"(r[2]), "=r"(r[3]) : "r"(a));
}
__device__ __forceinline__ void mma_bf16(float* c, const uint32_t* a, const uint32_t* b2) {
    asm volatile("mma.sync.aligned.m16n8k16.row.col.f32.bf16.bf16.f32 "
        "{%0,%1,%2,%3}, {%4,%5,%6,%7}, {%8,%9}, {%0,%1,%2,%3};"
        : "+f"(c[0]), "+f"(c[1]), "+f"(c[2]), "+f"(c[3])
        : "r"(a[0]), "r"(a[1]), "r"(a[2]), "r"(a[3]), "r"(b2[0]), "r"(b2[1]));
}
__device__ __forceinline__ void split_bf(float x, __nv_bfloat16& h, __nv_bfloat16& l) {
    h = __float2bfloat16(x);
    l = __float2bfloat16(x - __bfloat162float(h));
}
__device__ __forceinline__ void cpasync16(void* s, const void* g) {
    asm volatile("cp.async.ca.shared.global [%0], [%1], 16;"
        :: "r"(smem_u32(s)), "l"(g));
}
__device__ __forceinline__ void cp_commit() { asm volatile("cp.async.commit_group;"); }
template <int W>
__device__ __forceinline__ void cp_wait() { asm volatile("cp.async.wait_group %0;" :: "n"(W)); }

// ---------------- fused: layer1 (3->64, partial stats) + weight splits ----------------
#define MM1_BLOCKS 16384
__global__ void mm1_split_kernel(const float* __restrict__ x, const float* __restrict__ W1,
                                 float* __restrict__ y1,
                                 float* __restrict__ psum, float* __restrict__ psq,
                                 const float* __restrict__ W3, const float* __restrict__ Wc,
                                 __nv_bfloat16* __restrict__ W3h, __nv_bfloat16* __restrict__ W3l,
                                 __nv_bfloat16* __restrict__ Wch, __nv_bfloat16* __restrict__ Wcl)
{
    if (blockIdx.x >= MM1_BLOCKS) {
        int idx = (blockIdx.x - MM1_BLOCKS) * 256 + threadIdx.x;
        if (idx < 1024 * 128) {
            __nv_bfloat16 h, l;
            split_bf(W3[idx], h, l);
            W3h[idx] = h; W3l[idx] = l;
        } else {
            int j = idx - 1024 * 128;
            if (j < 1024 * 1024) {
                __nv_bfloat16 h, l;
                split_bf(Wc[j], h, l);
                Wch[j] = h; Wcl[j] = l;
            }
        }
        return;
    }
    int i = blockIdx.x * 256 + threadIdx.x;
    int n = i & 1023;
    int c = (i >> 10) & 63;
    int b = i >> 16;
    const float* xp = x + ((size_t)(b << 10) + n) * 3;
    const float* w = W1 + c * 3;
    float v = w[0] * xp[0] + w[1] * xp[1] + w[2] * xp[2];
    y1[i] = v;

    float s = v, sq = v * v;
    int lane = threadIdx.x & 31, warp = threadIdx.x >> 5;
#pragma unroll
    for (int off = 16; off; off >>= 1) {
        s += __shfl_xor_sync(0xffffffffu, s, off);
        sq += __shfl_xor_sync(0xffffffffu, sq, off);
    }
    __shared__ float ws[8], wq[8];
    if (lane == 0) { ws[warp] = s; wq[warp] = sq; }
    __syncthreads();
    if (threadIdx.x == 0) {
        float ts = 0.f, tq = 0.f;
#pragma unroll
        for (int w8 = 0; w8 < 8; w8++) { ts += ws[w8]; tq += wq[w8]; }
        int part = b * 4 + (blockIdx.x & 3);
        psum[c * 256 + part] = ts;
        psq[c * 256 + part] = tq;
    }
}

// ---------------- bn2relu(y2) -> bf16 hi/lo split ----------------
__global__ void bnrelu_split(const float* __restrict__ y2,
                             const float* __restrict__ s2, const float* __restrict__ sh2,
                             __nv_bfloat16* __restrict__ oh, __nv_bfloat16* __restrict__ ol)
{
    int i = blockIdx.x * 256 + threadIdx.x;
    if (i >= BATCH * 128 * NPTS) return;
    int c = (i >> 10) & 127;
    float r = fmaxf(0.f, fmaf(y2[i], s2[c], sh2[c]));
    __nv_bfloat16 h, l;
    split_bf(r, h, l);
    oh[i] = h; ol[i] = l;
}

// ---------------- reduce partial stats -> scale/shift ----------------
__global__ void reduce_parts(const float* __restrict__ psum, const float* __restrict__ psq,
                             int nparts, float countf,
                             const float* __restrict__ g, const float* __restrict__ bt,
                             float* __restrict__ scale, float* __restrict__ shift)
{
    int c = blockIdx.x;
    int t = threadIdx.x;
    double s = 0.0, sq = 0.0;
    for (int i = t; i < nparts; i += blockDim.x) {
        s += (double)psum[(size_t)c * nparts + i];
        sq += (double)psq[(size_t)c * nparts + i];
    }
    __shared__ double ss[128], ssq[128];
    ss[t] = s; ssq[t] = sq;
    __syncthreads();
    for (int off = 64; off; off >>= 1) {
        if (t < off) { ss[t] += ss[t + off]; ssq[t] += ssq[t + off]; }
        __syncthreads();
    }
    if (t == 0) {
        double count = (double)countf;
        double mean = ss[0] / count;
        double var = ssq[0] / count - mean * mean;
        float rs = rsqrtf((float)var + BN_EPS);
        float sc = g[c] * rs;
        scale[c] = sc;
        shift[c] = bt[c] - (float)mean * sc;
    }
}

// ---------------- fp32 fused SGEMM (layer2) ----------------
__global__ __launch_bounds__(256)
void sgemm_f(const float* __restrict__ A, const float* __restrict__ Bsrc,
             float* __restrict__ Cm, int M, int K, int N,
             const float* __restrict__ isc, const float* __restrict__ ish,
             float* __restrict__ psum, float* __restrict__ psq, int nparts)
{
    __shared__ float As[16][128];
    __shared__ float Bs[16][128];
    int b = blockIdx.z;
    int m0 = blockIdx.y * 128, n0 = blockIdx.x * 128;
    int t = threadIdx.x;
    int ty = t >> 4, tx = t & 15;
    int arow = t >> 1, acol = (t & 1) * 8;
    int brow = t >> 4, bcol = (t & 15) * 8;
    const float* Bb = Bsrc + (size_t)b * K * N;

    {
        const float* ap = A + (size_t)(m0 + arow) * K + acol;
        float4 a0 = *(const float4*)ap, a1 = *(const float4*)(ap + 4);
        As[acol + 0][arow] = a0.x; As[acol + 1][arow] = a0.y;
        As[acol + 2][arow] = a0.z; As[acol + 3][arow] = a0.w;
        As[acol + 4][arow] = a1.x; As[acol + 5][arow] = a1.y;
        As[acol + 6][arow] = a1.z; As[acol + 7][arow] = a1.w;
        const float* bp = Bb + (size_t)brow * N + n0 + bcol;
        float4 b0 = *(const float4*)bp, b1 = *(const float4*)(bp + 4);
        float s = isc[brow], sh = ish[brow];
        b0.x = fmaxf(0.f, fmaf(b0.x, s, sh)); b0.y = fmaxf(0.f, fmaf(b0.y, s, sh));
        b0.z = fmaxf(0.f, fmaf(b0.z, s, sh)); b0.w = fmaxf(0.f, fmaf(b0.w, s, sh));
        b1.x = fmaxf(0.f, fmaf(b1.x, s, sh)); b1.y = fmaxf(0.f, fmaf(b1.y, s, sh));
        b1.z = fmaxf(0.f, fmaf(b1.z, s, sh)); b1.w = fmaxf(0.f, fmaf(b1.w, s, sh));
        *(float4*)&Bs[brow][bcol] = b0;
        *(float4*)&Bs[brow][bcol + 4] = b1;
    }
    __syncthreads();

    float acc[8][8];
#pragma unroll
    for (int i = 0; i < 8; i++)
#pragma unroll
        for (int j = 0; j < 8; j++) acc[i][j] = 0.f;

    int nk = K >> 4;
    for (int kt = 0; kt < nk; kt++) {
        float4 ra0, ra1, rb0, rb1;
        bool has = (kt + 1 < nk);
        if (has) {
            int k0 = (kt + 1) << 4;
            const float* ap = A + (size_t)(m0 + arow) * K + k0 + acol;
            ra0 = *(const float4*)ap; ra1 = *(const float4*)(ap + 4);
            const float* bp = Bb + (size_t)(k0 + brow) * N + n0 + bcol;
            rb0 = *(const float4*)bp; rb1 = *(const float4*)(bp + 4);
            float s = isc[k0 + brow], sh = ish[k0 + brow];
            rb0.x = fmaxf(0.f, fmaf(rb0.x, s, sh)); rb0.y = fmaxf(0.f, fmaf(rb0.y, s, sh));
            rb0.z = fmaxf(0.f, fmaf(rb0.z, s, sh)); rb0.w = fmaxf(0.f, fmaf(rb0.w, s, sh));
            rb1.x = fmaxf(0.f, fmaf(rb1.x, s, sh)); rb1.y = fmaxf(0.f, fmaf(rb1.y, s, sh));
            rb1.z = fmaxf(0.f, fmaf(rb1.z, s, sh)); rb1.w = fmaxf(0.f, fmaf(rb1.w, s, sh));
        }
#pragma unroll
        for (int kk = 0; kk < 16; kk++) {
            float4 a0 = *(float4*)&As[kk][ty * 8];
            float4 a1 = *(float4*)&As[kk][ty * 8 + 4];
            float4 b0 = *(float4*)&Bs[kk][tx * 8];
            float4 b1 = *(float4*)&Bs[kk][tx * 8 + 4];
            float a[8] = {a0.x, a0.y, a0.z, a0.w, a1.x, a1.y, a1.z, a1.w};
            float bb[8] = {b0.x, b0.y, b0.z, b0.w, b1.x, b1.y, b1.z, b1.w};
#pragma unroll
            for (int i = 0; i < 8; i++)
#pragma unroll
                for (int j = 0; j < 8; j++) acc[i][j] = fmaf(a[i], bb[j], acc[i][j]);
        }
        __syncthreads();
        if (has) {
            As[acol + 0][arow] = ra0.x; As[acol + 1][arow] = ra0.y;
            As[acol + 2][arow] = ra0.z; As[acol + 3][arow] = ra0.w;
            As[acol + 4][arow] = ra1.x; As[acol + 5][arow] = ra1.y;
            As[acol + 6][arow] = ra1.z; As[acol + 7][arow] = ra1.w;
            *(float4*)&Bs[brow][bcol] = rb0;
            *(float4*)&Bs[brow][bcol + 4] = rb1;
            __syncthreads();
        }
    }

    float* cp = Cm + (size_t)b * M * N + (size_t)(m0 + ty * 8) * N + n0 + tx * 8;
#pragma unroll
    for (int i = 0; i < 8; i++) {
        *(float4*)(cp + (size_t)i * N) = make_float4(acc[i][0], acc[i][1], acc[i][2], acc[i][3]);
        *(float4*)(cp + (size_t)i * N + 4) = make_float4(acc[i][4], acc[i][5], acc[i][6], acc[i][7]);
    }
#pragma unroll
    for (int i = 0; i < 8; i++) {
        float s = 0.f, sq = 0.f;
#pragma unroll
        for (int j = 0; j < 8; j++) { float v = acc[i][j]; s += v; sq += v * v; }
#pragma unroll
        for (int off = 1; off < 16; off <<= 1) {
            s += __shfl_xor_sync(0xffffffffu, s, off);
            sq += __shfl_xor_sync(0xffffffffu, sq, off);
        }
        if (tx == 0) {
            int c = m0 + ty * 8 + i;
            int part = b * gridDim.x + blockIdx.x;
            psum[(size_t)c * nparts + part] = s;
            psq[(size_t)c * nparts + part] = sq;
        }
    }
}

// ---------------- bf16 tensor-core GEMM: BM=128 BN=128 BK=32, 4-stage, race-free 1 sync/iter ----
// MODE_EPI: 1 = bnrelu+split store; 3 = partials+arg; 4 = partials no arg.
#define BG_STAGE_ELEMS 18944   // A 2x5120 + B 2x4352
template <int MODE_EPI>
__global__ __launch_bounds__(256)
void bgemm3(const __nv_bfloat16* __restrict__ Ahg, const __nv_bfloat16* __restrict__ Alg,
            const __nv_bfloat16* __restrict__ Bhg, const __nv_bfloat16* __restrict__ Blg,
            __nv_bfloat16* __restrict__ Ch, __nv_bfloat16* __restrict__ Cl,
            int M, int K, int N,
            const float* __restrict__ osc, const float* __restrict__ osh,
            float* __restrict__ psum, float* __restrict__ psq,
            float* __restrict__ pmax, int* __restrict__ pamax,
            float* __restrict__ pmin, int* __restrict__ pamin,
            int nparts)
{
    extern __shared__ __nv_bfloat16 smb[];
    int t = threadIdx.x;
    int b = blockIdx.z;
    int m0 = blockIdx.y * 128, n0 = blockIdx.x * 128;
    int lane = t & 31, wid = t >> 5;
    int warpM = wid & 3, warpN = wid >> 2;
    int grp = lane >> 2, qt = lane & 3;
    const __nv_bfloat16* Bhb = Bhg + (size_t)b * K * N;
    const __nv_bfloat16* Blb = Blg + (size_t)b * K * N;

    int arowL = t & 127, acp = (t >> 7) * 16;
    int browL = t >> 3, bcolL = (t & 7) * 16;

    float acc[2][8][4];
#pragma unroll
    for (int i = 0; i < 2; i++)
#pragma unroll
        for (int j = 0; j < 8; j++)
#pragma unroll
            for (int e = 0; e < 4; e++) acc[i][j][e] = 0.f;

#define PA(st, hl) (smb + (st) * BG_STAGE_ELEMS + (hl) * 5120)
#define PB(st, hl) (smb + (st) * BG_STAGE_ELEMS + 10240 + (hl) * 4352)

    auto load_stage = [&](int st, int k0) {
        cpasync16(PA(st, 0) + arowL * 40 + acp,     Ahg + (size_t)(m0 + arowL) * K + k0 + acp);
        cpasync16(PA(st, 0) + arowL * 40 + acp + 8, Ahg + (size_t)(m0 + arowL) * K + k0 + acp + 8);
        cpasync16(PA(st, 1) + arowL * 40 + acp,     Alg + (size_t)(m0 + arowL) * K + k0 + acp);
        cpasync16(PA(st, 1) + arowL * 40 + acp + 8, Alg + (size_t)(m0 + arowL) * K + k0 + acp + 8);
        cpasync16(PB(st, 0) + browL * 136 + bcolL,     Bhb + (size_t)(k0 + browL) * N + n0 + bcolL);
        cpasync16(PB(st, 0) + browL * 136 + bcolL + 8, Bhb + (size_t)(k0 + browL) * N + n0 + bcolL + 8);
        cpasync16(PB(st, 1) + browL * 136 + bcolL,     Blb + (size_t)(k0 + browL) * N + n0 + bcolL);
        cpasync16(PB(st, 1) + browL * 136 + bcolL + 8, Blb + (size_t)(k0 + browL) * N + n0 + bcolL + 8);
    };

    int nk = K >> 5;   // 4 for layer3/crit, 32 for Wc
    load_stage(0, 0);
    cp_commit();
    load_stage(1, 32);
    cp_commit();
    load_stage(2, 64);
    cp_commit();

    for (int kt = 0; kt < nk; kt++) {
        int cur = kt & 3;
        cp_wait<2>();         // group kt complete (3 prologue commits + 1/iter)
        __syncthreads();      // all warps done reading stage (kt-1)&3 == (kt+3)&3
        if (kt + 3 < nk) load_stage((kt + 3) & 3, (kt + 3) << 5);
        cp_commit();          // uniform group count (empty group past the end)

#pragma unroll
        for (int ks = 0; ks < 2; ks++) {
            int kk = ks * 16;
            uint32_t ah[2][4], al[2][4];
#pragma unroll
            for (int i = 0; i < 2; i++) {
                int mr = warpM * 32 + i * 16 + (lane & 15);
                int mc = kk + (lane >> 4) * 8;
                ldsm_x4(ah[i], smem_u32(PA(cur, 0) + mr * 40 + mc));
                ldsm_x4(al[i], smem_u32(PA(cur, 1) + mr * 40 + mc));
            }
            uint32_t bh[8][2], bl[8][2];
#pragma unroll
            for (int p = 0; p < 4; p++) {
                int kr = kk + (lane & 15);
                int nc = warpN * 64 + p * 16 + (lane >> 4) * 8;
                uint32_t r[4];
                ldsm_x4_t(r, smem_u32(PB(cur, 0) + kr * 136 + nc));
                bh[p * 2][0] = r[0]; bh[p * 2][1] = r[1];
                bh[p * 2 + 1][0] = r[2]; bh[p * 2 + 1][1] = r[3];
                ldsm_x4_t(r, smem_u32(PB(cur, 1) + kr * 136 + nc));
                bl[p * 2][0] = r[0]; bl[p * 2][1] = r[1];
                bl[p * 2 + 1][0] = r[2]; bl[p * 2 + 1][1] = r[3];
            }
#pragma unroll
            for (int i = 0; i < 2; i++)
#pragma unroll
                for (int j = 0; j < 8; j++) {
                    mma_bf16(acc[i][j], ah[i], bh[j]);
                    mma_bf16(acc[i][j], ah[i], bl[j]);
                    mma_bf16(acc[i][j], al[i], bh[j]);
                }
        }
    }
    __syncthreads();   // all warps done with smem before epilogue aliasing

    if (MODE_EPI == 1) {
#pragma unroll
        for (int i = 0; i < 2; i++)
#pragma unroll
            for (int half = 0; half < 2; half++) {
                int c = m0 + warpM * 32 + i * 16 + grp + half * 8;
                float s = osc[c], sh = osh[c];
#pragma unroll
                for (int j = 0; j < 8; j++) {
                    float v0 = fmaxf(0.f, fmaf(acc[i][j][half * 2], s, sh));
                    float v1 = fmaxf(0.f, fmaf(acc[i][j][half * 2 + 1], s, sh));
                    __nv_bfloat16 h0, l0, h1, l1;
                    split_bf(v0, h0, l0);
                    split_bf(v1, h1, l1);
                    int n = n0 + warpN * 64 + j * 8 + qt * 2;
                    size_t idx = (size_t)b * M * N + (size_t)c * N + n;
                    __nv_bfloat162 ph; ph.x = h0; ph.y = h1;
                    __nv_bfloat162 pl; pl.x = l0; pl.y = l1;
                    *(__nv_bfloat162*)&Ch[idx] = ph;
                    *(__nv_bfloat162*)&Cl[idx] = pl;
                }
            }
    } else {
        float* eS  = (float*)smb;
        float* eQ  = eS + 256;
        float* eMx = eQ + 256;
        float* eMn = eMx + 256;
        int*   eAx = (int*)(eMn + 256);
        int*   eAn = eAx + 256;
#pragma unroll
        for (int i = 0; i < 2; i++)
#pragma unroll
            for (int half = 0; half < 2; half++) {
                float s = 0.f, sq = 0.f;
                float mx = -INFINITY, mn = INFINITY;
                int amx = 0, amn = 0;
#pragma unroll
                for (int j = 0; j < 8; j++)
#pragma unroll
                    for (int e = 0; e < 2; e++) {
                        float v = acc[i][j][half * 2 + e];
                        int n = n0 + warpN * 64 + j * 8 + qt * 2 + e;
                        s += v; sq += v * v;
                        if (v > mx) { mx = v; amx = n; }
                        if (v < mn) { mn = v; amn = n; }
                    }
#pragma unroll
                for (int off = 1; off < 4; off <<= 1) {
                    s += __shfl_xor_sync(0xffffffffu, s, off);
                    sq += __shfl_xor_sync(0xffffffffu, sq, off);
                    float ov = __shfl_xor_sync(0xffffffffu, mx, off);
                    int   oa = __shfl_xor_sync(0xffffffffu, amx, off);
                    if (ov > mx || (ov == mx && oa < amx)) { mx = ov; amx = oa; }
                    ov = __shfl_xor_sync(0xffffffffu, mn, off);
                    oa = __shfl_xor_sync(0xffffffffu, amn, off);
                    if (ov < mn || (ov == mn && oa < amn)) { mn = ov; amn = oa; }
                }
                if (qt == 0) {
                    int r = warpM * 32 + i * 16 + grp + half * 8;
                    eS[r * 2 + warpN] = s; eQ[r * 2 + warpN] = sq;
                    eMx[r * 2 + warpN] = mx; eMn[r * 2 + warpN] = mn;
                    eAx[r * 2 + warpN] = amx; eAn[r * 2 + warpN] = amn;
                }
            }
        __syncthreads();
        if (t < 128) {
            float s = eS[t * 2] + eS[t * 2 + 1];
            float sq = eQ[t * 2] + eQ[t * 2 + 1];
            float m0v = eMx[t * 2], m1v = eMx[t * 2 + 1];
            int a0 = eAx[t * 2], a1 = eAx[t * 2 + 1];
            float mx; int amx;
            if (m1v > m0v || (m1v == m0v && a1 < a0)) { mx = m1v; amx = a1; }
            else { mx = m0v; amx = a0; }
            float n0v = eMn[t * 2], n1v = eMn[t * 2 + 1];
            int b0 = eAn[t * 2], b1 = eAn[t * 2 + 1];
            float mn; int amn;
            if (n1v < n0v || (n1v == n0v && b1 < b0)) { mn = n1v; amn = b1; }
            else { mn = n0v; amn = b0; }
            int c = m0 + t;
            int part = b * gridDim.x + blockIdx.x;
            psum[(size_t)c * nparts + part] = s;
            psq[(size_t)c * nparts + part] = sq;
            size_t pi = ((size_t)((b << 10) + c)) * gridDim.x + blockIdx.x;
            pmax[pi] = mx; pmin[pi] = mn;
            if (MODE_EPI == 3) { pamax[pi] = amx; pamin[pi] = amn; }
        }
    }
#undef PA
#undef PB
}

// ---------------- CPL selection from partial max/min (8 tiles) ----------------
__global__ __launch_bounds__(256)
void cpl2_kernel(const float* __restrict__ pmax, const int* __restrict__ pamax,
                 const float* __restrict__ pmin, const int* __restrict__ pamin,
                 const float* __restrict__ sc3, const float* __restrict__ sh3,
                 int* __restrict__ outidx)
{
    __shared__ float s_val[1024];
    __shared__ int   s_aidx[1024];
    __shared__ float s_scores[1024];
    __shared__ float s_key[1024];
    __shared__ int   s_idx[1024];
    __shared__ int   s_packed[1024];
    __shared__ int   s_wsum[8];
    __shared__ int   s_m;

    int b = blockIdx.x;
    int t = threadIdx.x, lane = t & 31, warp = t >> 5;

    for (int c = t; c < 1024; c += 256) {
        float s3 = sc3[c], s3h = sh3[c];
        size_t base = ((size_t)((b << 10) + c)) * 8;
        float v; int a;
        if (s3 > 0.f) {
            v = pmax[base]; a = pamax[base];
#pragma unroll
            for (int nt = 1; nt < 8; nt++) {
                float ov = pmax[base + nt]; int oa = pamax[base + nt];
                if (ov > v || (ov == v && oa < a)) { v = ov; a = oa; }
            }
        } else {
            v = pmin[base]; a = pamin[base];
#pragma unroll
            for (int nt = 1; nt < 8; nt++) {
                float ov = pmin[base + nt]; int oa = pamin[base + nt];
                if (ov < v || (ov == v && oa < a)) { v = ov; a = oa; }
            }
        }
        s_val[c] = fmaxf(0.f, fmaf(v, s3, s3h));
        s_aidx[c] = a;
    }
    __syncthreads();

    float sc0 = 0.f, sc1 = 0.f, sc2 = 0.f, sc3q = 0.f;
    for (int c = 0; c < 1024; c++) {
        int ai = s_aidx[c];
        if ((ai & 255) == t) {
            float v = s_val[c];
            int q = ai >> 8;
            if (q == 0) sc0 += v; else if (q == 1) sc1 += v;
            else if (q == 2) sc2 += v; else sc3q += v;
        }
    }
    {
        float scq[4] = {sc0, sc1, sc2, sc3q};
#pragma unroll
        for (int q = 0; q < 4; q++) {
            int n = t + (q << 8);
            s_scores[n] = scq[q];
            s_key[n] = -scq[q] + CPL_EPS * (float)n;
            s_idx[n] = n;
        }
    }
    __syncthreads();

    for (int k = 2; k <= 1024; k <<= 1) {
        for (int j = k >> 1; j > 0; j >>= 1) {
#pragma unroll
            for (int base = t; base < 1024; base += 256) {
                int l = base ^ j;
                if (l > base) {
                    bool asc = ((base & k) == 0);
                    float k1 = s_key[base], k2 = s_key[l];
                    int i1 = s_idx[base], i2 = s_idx[l];
                    bool gt = (k1 > k2) || (k1 == k2 && i1 > i2);
                    if (gt == asc) {
                        s_key[base] = k2; s_key[l] = k1;
                        s_idx[base] = i2; s_idx[l] = i1;
                    }
                }
            }
            __syncthreads();
        }
    }

    int f0, f1, f2, f3, loc;
    int base4 = t * 4;
    f0 = (s_scores[s_idx[base4 + 0]] > 0.f) ? 1 : 0;
    f1 = (s_scores[s_idx[base4 + 1]] > 0.f) ? 1 : 0;
    f2 = (s_scores[s_idx[base4 + 2]] > 0.f) ? 1 : 0;
    f3 = (s_scores[s_idx[base4 + 3]] > 0.f) ? 1 : 0;
    loc = f0 + f1 + f2 + f3;
    int incl = loc;
#pragma unroll
    for (int off = 1; off < 32; off <<= 1) {
        int v = __shfl_up_sync(0xffffffffu, incl, off);
        if (lane >= off) incl += v;
    }
    if (lane == 31) s_wsum[warp] = incl;
    __syncthreads();
    if (t == 0) {
        int run = 0;
        for (int w = 0; w < 8; w++) { int v = s_wsum[w]; s_wsum[w] = run; run += v; }
        s_m = run;
    }
    __syncthreads();
    int m = s_m;
    int run = s_wsum[warp] + (incl - loc);
    {
        int fq[4] = {f0, f1, f2, f3};
#pragma unroll
        for (int q = 0; q < 4; q++) {
            int i = base4 + q;
            int pos = fq[q] ? run : (m + i - run);
            s_packed[pos] = s_idx[i];
            run += fq[q];
        }
    }
    __syncthreads();

    float m_eff = (m > 0) ? (float)m : (float)NPTS;
    int p;
    if (m_eff >= (float)KCPL) {
        p = t;
    } else {
        float lin = ((float)t * (m_eff - 1.0f)) / (float)(KCPL - 1);
        int pmaxv = (int)(m_eff - 1.0f);
        int r = (int)rintf(lin);
        p = min(max(r, 0), pmaxv);
    }
    outidx[b * KCPL + t] = s_packed[p];
}

// ---------------- gather split bn2relu(y2)[:, idx] -> h2g ----------------
__global__ void gather_kernel(const __nv_bfloat16* __restrict__ h3bh,
                              const __nv_bfloat16* __restrict__ h3bl,
                              const int* __restrict__ cidx,
                              __nv_bfloat16* __restrict__ h2gh, __nv_bfloat16* __restrict__ h2gl)
{
    int i = blockIdx.x * blockDim.x + threadIdx.x;
    if (i >= BATCH * 128 * KCPL) return;
    int j = i & 255;
    int k = (i >> 8) & 127;
    int b = i >> 15;
    int col = cidx[(b << 8) + j];
    size_t src = (((size_t)(b * 128 + k)) << 10) + col;
    h2gh[i] = h3bh[src];
    h2gl[i] = h3bl[src];
}

// ---------------- gfeat from Wc partial max/min (2 tiles) ----------------
__global__ void gfeat_kernel(const float* __restrict__ pmax, const float* __restrict__ pmin,
                             const float* __restrict__ scale, const float* __restrict__ shift,
                             float* __restrict__ gfeat)
{
    int i = blockIdx.x * 256 + threadIdx.x;
    if (i >= BATCH * 1024) return;
    int c = i & 1023;
    float s = scale[c], sh = shift[c];
    size_t base = (size_t)i * 2;
    float v;
    if (s > 0.f) v = fmaxf(pmax[base], pmax[base + 1]);
    else         v = fminf(pmin[base], pmin[base + 1]);
    gfeat[i] = fmaxf(0.f, fmaf(v, s, sh));
}

// ---------------- FC + batch-axis BN + relu (256 threads: 4 per batch) ----------------
__global__ __launch_bounds__(256)
void fc_bn_relu_kernel(const float* __restrict__ in,
                       const float* __restrict__ W,
                       const float* __restrict__ bias,
                       const float* __restrict__ g,
                       const float* __restrict__ bb,
                       float* __restrict__ out, int Cin)
{
    int c = blockIdx.x;
    int t = threadIdx.x;
    int b = t & 63, q = t >> 6;
    int Cout = gridDim.x;
    int chunk = Cin >> 2;
    const float* w = W + (size_t)c * Cin + q * chunk;
    const float* xb = in + (size_t)b * Cin + q * chunk;
    float acc = 0.f;
    for (int j = 0; j < chunk; j++) acc = fmaf(xb[j], w[j], acc);
    __shared__ float part[4][64];
    __shared__ float sy[64];
    __shared__ float s_scale, s_shift;
    part[q][b] = acc;
    __syncthreads();
    if (t < 64) {
        float a = part[0][t] + part[1][t] + part[2][t] + part[3][t] + bias[c];
        sy[t] = a;
    }
    __syncthreads();
    if (t == 0) {
        double s = 0.0, sq = 0.0;
        for (int i = 0; i < 64; i++) { s += sy[i]; sq += (double)sy[i] * sy[i]; }
        double mean = s / 64.0;
        double var = sq / 64.0 - mean * mean;
        float rs = rsqrtf((float)var + BN_EPS);
        float scl = g[c] * rs;
        s_scale = scl;
        s_shift = bb[c] - (float)mean * scl;
    }
    __syncthreads();
    if (t < 64)
        out[(size_t)t * Cout + c] = fmaxf(0.f, fmaf(sy[t], s_scale, s_shift));
}

// ---------------- final FC ----------------
__global__ void fc3_kernel(const float* __restrict__ in, const float* __restrict__ W,
                           const float* __restrict__ bias, float* __restrict__ out)
{
    int i = blockIdx.x * blockDim.x + threadIdx.x;
    if (i >= BATCH * NCLS) return;
    int b = i / NCLS, j = i - b * NCLS;
    float acc = bias[j];
    const float* xb = in + (size_t)b * 256;
    const float* w = W + (size_t)j * 256;
    for (int t = 0; t < 256; t++) acc = fmaf(xb[t], w[t], acc);
    out[i] = acc;
}

// ---------------- launch ----------------
extern "C" void kernel_launch(void* const* d_in, const int* in_sizes, int n_in,
                              void* d_out, int out_size)
{
    const float* x     = (const float*)d_in[0];
    const float* W1    = (const float*)d_in[1];
    const float* g1    = (const float*)d_in[2];
    const float* b1    = (const float*)d_in[3];
    const float* W2    = (const float*)d_in[4];
    const float* g2    = (const float*)d_in[5];
    const float* b2    = (const float*)d_in[6];
    const float* W3    = (const float*)d_in[7];
    const float* g3    = (const float*)d_in[8];
    const float* b3    = (const float*)d_in[9];
    const float* Wc    = (const float*)d_in[10];
    const float* gc    = (const float*)d_in[11];
    const float* bc    = (const float*)d_in[12];
    const float* fc1_w = (const float*)d_in[13];
    const float* fc1_b = (const float*)d_in[14];
    const float* bn1_g = (const float*)d_in[15];
    const float* bn1_b = (const float*)d_in[16];
    const float* fc2_w = (const float*)d_in[17];
    const float* fc2_b = (const float*)d_in[18];
    const float* bn2_g = (const float*)d_in[19];
    const float* bn2_b = (const float*)d_in[20];
    const float* fc3_w = (const float*)d_in[21];
    const float* fc3_b = (const float*)d_in[22];
    float* out = (float*)d_out;

    float *p_y1, *p_y2, *p_gfeat, *p_fc1h, *p_fc2h, *p_bn;
    float *p_psum3, *p_psq3, *p_pmax, *p_pmin, *p_psumc, *p_psqc;
    int *p_cidx, *p_pamax, *p_pamin;
    __nv_bfloat16 *p_h3bh, *p_h3bl, *p_h2gh, *p_h2gl, *p_crith, *p_critl;
    __nv_bfloat16 *p_W3h, *p_W3l, *p_Wch, *p_Wcl;
    cudaGetSymbolAddress((void**)&p_y1, g_y1);
    cudaGetSymbolAddress((void**)&p_y2, g_y2);
    cudaGetSymbolAddress((void**)&p_h3bh, g_h3bh);
    cudaGetSymbolAddress((void**)&p_h3bl, g_h3bl);
    cudaGetSymbolAddress((void**)&p_h2gh, g_h2gh);
    cudaGetSymbolAddress((void**)&p_h2gl, g_h2gl);
    cudaGetSymbolAddress((void**)&p_crith, g_crith);
    cudaGetSymbolAddress((void**)&p_critl, g_critl);
    cudaGetSymbolAddress((void**)&p_W3h, g_W3h);
    cudaGetSymbolAddress((void**)&p_W3l, g_W3l);
    cudaGetSymbolAddress((void**)&p_Wch, g_Wch);
    cudaGetSymbolAddress((void**)&p_Wcl, g_Wcl);
    cudaGetSymbolAddress((void**)&p_gfeat, g_gfeat);
    cudaGetSymbolAddress((void**)&p_fc1h, g_fc1h);
    cudaGetSymbolAddress((void**)&p_fc2h, g_fc2h);
    cudaGetSymbolAddress((void**)&p_bn, g_bn);
    cudaGetSymbolAddress((void**)&p_psum3, g_psum3);
    cudaGetSymbolAddress((void**)&p_psq3, g_psq3);
    cudaGetSymbolAddress((void**)&p_pmax, g_pmax);
    cudaGetSymbolAddress((void**)&p_pamax, g_pamax);
    cudaGetSymbolAddress((void**)&p_pmin, g_pmin);
    cudaGetSymbolAddress((void**)&p_pamin, g_pamin);
    cudaGetSymbolAddress((void**)&p_psumc, g_psumc);
    cudaGetSymbolAddress((void**)&p_psqc, g_psqc);
    cudaGetSymbolAddress((void**)&p_cidx, g_cidx);

    const int BG_SMEM = 4 * BG_STAGE_ELEMS * 2;   // 151552 bytes
    cudaFuncSetAttribute(bgemm3<1>, cudaFuncAttributeMaxDynamicSharedMemorySize, BG_SMEM);
    cudaFuncSetAttribute(bgemm3<3>, cudaFuncAttributeMaxDynamicSharedMemorySize, BG_SMEM);
    cudaFuncSetAttribute(bgemm3<4>, cudaFuncAttributeMaxDynamicSharedMemorySize, BG_SMEM);

    float* s1  = p_bn + 0 * 1024;
    float* sh1 = p_bn + 1 * 1024;
    float* s2  = p_bn + 2 * 1024;
    float* sh2 = p_bn + 3 * 1024;
    float* s3  = p_bn + 4 * 1024;
    float* sh3 = p_bn + 5 * 1024;
    float* scc = p_bn + 6 * 1024;
    float* shc = p_bn + 7 * 1024;

    mm1_split_kernel<<<MM1_BLOCKS + 4608, 256>>>(x, W1, p_y1, p_psum3, p_psq3,
                                                 W3, Wc, p_W3h, p_W3l, p_Wch, p_Wcl);
    reduce_parts<<<64, 128>>>(p_psum3, p_psq3, 256, (float)(BATCH * NPTS), g1, b1, s1, sh1);
    sgemm_f<<<dim3(8, 1, 64), 256>>>(W2, p_y1, p_y2, 128, 64, NPTS,
                                     s1, sh1, p_psum3, p_psq3, 512);
    reduce_parts<<<128, 128>>>(p_psum3, p_psq3, 512, (float)(BATCH * NPTS), g2, b2, s2, sh2);
    bnrelu_split<<<BATCH * 128 * NPTS / 256, 256>>>(p_y2, s2, sh2, p_h3bh, p_h3bl);
    bgemm3<3><<<dim3(8, 8, 64), 256, BG_SMEM>>>(p_W3h, p_W3l, p_h3bh, p_h3bl,
                                                nullptr, nullptr, 1024, 128, 1024,
                                                nullptr, nullptr,
                                                p_psum3, p_psq3, p_pmax, p_pamax, p_pmin, p_pamin, 512);
    reduce_parts<<<1024, 128>>>(p_psum3, p_psq3, 512, (float)(BATCH * NPTS), g3, b3, s3, sh3);
    cpl2_kernel<<<BATCH, 256>>>(p_pmax, p_pamax, p_pmin, p_pamin, s3, sh3, p_cidx);
    gather_kernel<<<(BATCH * 128 * KCPL + 255) / 256, 256>>>(p_h3bh, p_h3bl, p_cidx, p_h2gh, p_h2gl);
    bgemm3<1><<<dim3(2, 8, 64), 256, BG_SMEM>>>(p_W3h, p_W3l, p_h2gh, p_h2gl,
                                                p_crith, p_critl, 1024, 128, KCPL,
                                                s3, sh3,
                                                nullptr, nullptr, nullptr, nullptr, nullptr, nullptr, 0);
    bgemm3<4><<<dim3(2, 8, 64), 256, BG_SMEM>>>(p_Wch, p_Wcl, p_crith, p_critl,
                                                nullptr, nullptr, 1024, 1024, KCPL,
                                                nullptr, nullptr,
                                                p_psumc, p_psqc, p_pmax, nullptr, p_pmin, nullptr, 128);
    reduce_parts<<<1024, 128>>>(p_psumc, p_psqc, 128, (float)(BATCH * KCPL), gc, bc, scc, shc);
    gfeat_kernel<<<(BATCH * 1024 + 255) / 256, 256>>>(p_pmax, p_pmin, scc, shc, p_gfeat);
    fc_bn_relu_kernel<<<512, 256>>>(p_gfeat, fc1_w, fc1_b, bn1_g, bn1_b, p_fc1h, 1024);
    fc_bn_relu_kernel<<<256, 256>>>(p_fc1h, fc2_w, fc2_b, bn2_g, bn2_b, p_fc2h, 512);
    fc3_kernel<<<(BATCH * NCLS + 255) / 256, 256>>>(p_fc2h, fc3_w, fc3_b, out);
}

// round 15
// speedup vs baseline: 1.0346x; 1.0346x over previous
#include <cuda_runtime.h>
#include <cuda_bf16.h>
#include <math.h>
#include <stdint.h>

// ---------------- problem constants ----------------
#define BATCH 64
#define NPTS  1024
#define KCPL  256
#define NCLS  40
#define BN_EPS 1e-5f
#define CPL_EPS 1e-7f

// ---------------- device scratch ----------------
__device__ float g_y1[BATCH * 64 * NPTS];
__device__ float g_y2[BATCH * 128 * NPTS];
__device__ __nv_bfloat16 g_h3bh[BATCH * 128 * NPTS];
__device__ __nv_bfloat16 g_h3bl[BATCH * 128 * NPTS];
__device__ __nv_bfloat16 g_h2gh[BATCH * 128 * KCPL];
__device__ __nv_bfloat16 g_h2gl[BATCH * 128 * KCPL];
__device__ __nv_bfloat16 g_crith[(size_t)BATCH * 1024 * KCPL];
__device__ __nv_bfloat16 g_critl[(size_t)BATCH * 1024 * KCPL];
__device__ __nv_bfloat16 g_W3h[1024 * 128], g_W3l[1024 * 128];
__device__ __nv_bfloat16 g_Wch[1024 * 1024], g_Wcl[1024 * 1024];
__device__ float g_psum3[1024 * 1024];
__device__ float g_psq3[1024 * 1024];
__device__ float g_pmax[BATCH * 1024 * 16];
__device__ int   g_pamax[BATCH * 1024 * 16];
__device__ float g_pmin[BATCH * 1024 * 16];
__device__ int   g_pamin[BATCH * 1024 * 16];
__device__ float g_psumc[1024 * 256];
__device__ float g_psqc[1024 * 256];
__device__ float g_gfeat[BATCH * 1024];
__device__ float g_fc1h[BATCH * 512];
__device__ float g_fc2h[BATCH * 256];
__device__ int   g_cidx[BATCH * KCPL];
__device__ float g_bn[8 * 1024];

// ---------------- ptx helpers ----------------
__device__ __forceinline__ uint32_t smem_u32(const void* p) {
    return (uint32_t)__cvta_generic_to_shared(p);
}
__device__ __forceinline__ void ldsm_x4(uint32_t* r, uint32_t a) {
    asm volatile("ldmatrix.sync.aligned.m8n8.x4.shared.b16 {%0,%1,%2,%3}, [%4];"
        : "=r"(r[0]), "=r"(r[1]), "=r"(r[2]), "=r"(r[3]) : "r"(a));
}
__device__ __forceinline__ void ldsm_x4_t(uint32_t* r, uint32_t a) {
    asm volatile("ldmatrix.sync.aligned.m8n8.x4.trans.shared.b16 {%0,%1,%2,%3}, [%4];"
        : "=r"(r[0]), "=r"(r[1]), "=r"(r[2]), "=r"(r[3]) : "r"(a));
}
__device__ __forceinline__ void mma_bf16(float* c, const uint32_t* a, const uint32_t* b2) {
    asm volatile("mma.sync.aligned.m16n8k16.row.col.f32.bf16.bf16.f32 "
        "{%0,%1,%2,%3}, {%4,%5,%6,%7}, {%8,%9}, {%0,%1,%2,%3};"
        : "+f"(c[0]), "+f"(c[1]), "+f"(c[2]), "+f"(c[3])
        : "r"(a[0]), "r"(a[1]), "r"(a[2]), "r"(a[3]), "r"(b2[0]), "r"(b2[1]));
}
__device__ __forceinline__ void split_bf(float x, __nv_bfloat16& h, __nv_bfloat16& l) {
    h = __float2bfloat16(x);
    l = __float2bfloat16(x - __bfloat162float(h));
}
__device__ __forceinline__ void cpasync16(void* s, const void* g) {
    asm volatile("cp.async.ca.shared.global [%0], [%1], 16;"
        :: "r"(smem_u32(s)), "l"(g));
}
__device__ __forceinline__ void cp_commit() { asm volatile("cp.async.commit_group;"); }
template <int W>
__device__ __forceinline__ void cp_wait() { asm volatile("cp.async.wait_group %0;" :: "n"(W)); }

// ---------------- fused: layer1 (3->64, partial stats) + weight splits ----------------
#define MM1_BLOCKS 16384
__global__ void mm1_split_kernel(const float* __restrict__ x, const float* __restrict__ W1,
                                 float* __restrict__ y1,
                                 float* __restrict__ psum, float* __restrict__ psq,
                                 const float* __restrict__ W3, const float* __restrict__ Wc,
                                 __nv_bfloat16* __restrict__ W3h, __nv_bfloat16* __restrict__ W3l,
                                 __nv_bfloat16* __restrict__ Wch, __nv_bfloat16* __restrict__ Wcl)
{
    if (blockIdx.x >= MM1_BLOCKS) {
        int idx = (blockIdx.x - MM1_BLOCKS) * 256 + threadIdx.x;
        if (idx < 1024 * 128) {
            __nv_bfloat16 h, l;
            split_bf(W3[idx], h, l);
            W3h[idx] = h; W3l[idx] = l;
        } else {
            int j = idx - 1024 * 128;
            if (j < 1024 * 1024) {
                __nv_bfloat16 h, l;
                split_bf(Wc[j], h, l);
                Wch[j] = h; Wcl[j] = l;
            }
        }
        return;
    }
    int i = blockIdx.x * 256 + threadIdx.x;
    int n = i & 1023;
    int c = (i >> 10) & 63;
    int b = i >> 16;
    const float* xp = x + ((size_t)(b << 10) + n) * 3;
    const float* w = W1 + c * 3;
    float v = w[0] * xp[0] + w[1] * xp[1] + w[2] * xp[2];
    y1[i] = v;

    float s = v, sq = v * v;
    int lane = threadIdx.x & 31, warp = threadIdx.x >> 5;
#pragma unroll
    for (int off = 16; off; off >>= 1) {
        s += __shfl_xor_sync(0xffffffffu, s, off);
        sq += __shfl_xor_sync(0xffffffffu, sq, off);
    }
    __shared__ float ws[8], wq[8];
    if (lane == 0) { ws[warp] = s; wq[warp] = sq; }
    __syncthreads();
    if (threadIdx.x == 0) {
        float ts = 0.f, tq = 0.f;
#pragma unroll
        for (int w8 = 0; w8 < 8; w8++) { ts += ws[w8]; tq += wq[w8]; }
        int part = b * 4 + (blockIdx.x & 3);
        psum[c * 256 + part] = ts;
        psq[c * 256 + part] = tq;
    }
}

// ---------------- bn2relu(y2) -> bf16 hi/lo split ----------------
__global__ void bnrelu_split(const float* __restrict__ y2,
                             const float* __restrict__ s2, const float* __restrict__ sh2,
                             __nv_bfloat16* __restrict__ oh, __nv_bfloat16* __restrict__ ol)
{
    int i = blockIdx.x * 256 + threadIdx.x;
    if (i >= BATCH * 128 * NPTS) return;
    int c = (i >> 10) & 127;
    float r = fmaxf(0.f, fmaf(y2[i], s2[c], sh2[c]));
    __nv_bfloat16 h, l;
    split_bf(r, h, l);
    oh[i] = h; ol[i] = l;
}

// ---------------- reduce partial stats -> scale/shift ----------------
__global__ void reduce_parts(const float* __restrict__ psum, const float* __restrict__ psq,
                             int nparts, float countf,
                             const float* __restrict__ g, const float* __restrict__ bt,
                             float* __restrict__ scale, float* __restrict__ shift)
{
    int c = blockIdx.x;
    int t = threadIdx.x;
    double s = 0.0, sq = 0.0;
    for (int i = t; i < nparts; i += blockDim.x) {
        s += (double)psum[(size_t)c * nparts + i];
        sq += (double)psq[(size_t)c * nparts + i];
    }
    __shared__ double ss[128], ssq[128];
    ss[t] = s; ssq[t] = sq;
    __syncthreads();
    for (int off = 64; off; off >>= 1) {
        if (t < off) { ss[t] += ss[t + off]; ssq[t] += ssq[t + off]; }
        __syncthreads();
    }
    if (t == 0) {
        double count = (double)countf;
        double mean = ss[0] / count;
        double var = ssq[0] / count - mean * mean;
        float rs = rsqrtf((float)var + BN_EPS);
        float sc = g[c] * rs;
        scale[c] = sc;
        shift[c] = bt[c] - (float)mean * sc;
    }
}

// ---------------- fp32 fused SGEMM (layer2) ----------------
__global__ __launch_bounds__(256)
void sgemm_f(const float* __restrict__ A, const float* __restrict__ Bsrc,
             float* __restrict__ Cm, int M, int K, int N,
             const float* __restrict__ isc, const float* __restrict__ ish,
             float* __restrict__ psum, float* __restrict__ psq, int nparts)
{
    __shared__ float As[16][128];
    __shared__ float Bs[16][128];
    int b = blockIdx.z;
    int m0 = blockIdx.y * 128, n0 = blockIdx.x * 128;
    int t = threadIdx.x;
    int ty = t >> 4, tx = t & 15;
    int arow = t >> 1, acol = (t & 1) * 8;
    int brow = t >> 4, bcol = (t & 15) * 8;
    const float* Bb = Bsrc + (size_t)b * K * N;

    {
        const float* ap = A + (size_t)(m0 + arow) * K + acol;
        float4 a0 = *(const float4*)ap, a1 = *(const float4*)(ap + 4);
        As[acol + 0][arow] = a0.x; As[acol + 1][arow] = a0.y;
        As[acol + 2][arow] = a0.z; As[acol + 3][arow] = a0.w;
        As[acol + 4][arow] = a1.x; As[acol + 5][arow] = a1.y;
        As[acol + 6][arow] = a1.z; As[acol + 7][arow] = a1.w;
        const float* bp = Bb + (size_t)brow * N + n0 + bcol;
        float4 b0 = *(const float4*)bp, b1 = *(const float4*)(bp + 4);
        float s = isc[brow], sh = ish[brow];
        b0.x = fmaxf(0.f, fmaf(b0.x, s, sh)); b0.y = fmaxf(0.f, fmaf(b0.y, s, sh));
        b0.z = fmaxf(0.f, fmaf(b0.z, s, sh)); b0.w = fmaxf(0.f, fmaf(b0.w, s, sh));
        b1.x = fmaxf(0.f, fmaf(b1.x, s, sh)); b1.y = fmaxf(0.f, fmaf(b1.y, s, sh));
        b1.z = fmaxf(0.f, fmaf(b1.z, s, sh)); b1.w = fmaxf(0.f, fmaf(b1.w, s, sh));
        *(float4*)&Bs[brow][bcol] = b0;
        *(float4*)&Bs[brow][bcol + 4] = b1;
    }
    __syncthreads();

    float acc[8][8];
#pragma unroll
    for (int i = 0; i < 8; i++)
#pragma unroll
        for (int j = 0; j < 8; j++) acc[i][j] = 0.f;

    int nk = K >> 4;
    for (int kt = 0; kt < nk; kt++) {
        float4 ra0, ra1, rb0, rb1;
        bool has = (kt + 1 < nk);
        if (has) {
            int k0 = (kt + 1) << 4;
            const float* ap = A + (size_t)(m0 + arow) * K + k0 + acol;
            ra0 = *(const float4*)ap; ra1 = *(const float4*)(ap + 4);
            const float* bp = Bb + (size_t)(k0 + brow) * N + n0 + bcol;
            rb0 = *(const float4*)bp; rb1 = *(const float4*)(bp + 4);
            float s = isc[k0 + brow], sh = ish[k0 + brow];
            rb0.x = fmaxf(0.f, fmaf(rb0.x, s, sh)); rb0.y = fmaxf(0.f, fmaf(rb0.y, s, sh));
            rb0.z = fmaxf(0.f, fmaf(rb0.z, s, sh)); rb0.w = fmaxf(0.f, fmaf(rb0.w, s, sh));
            rb1.x = fmaxf(0.f, fmaf(rb1.x, s, sh)); rb1.y = fmaxf(0.f, fmaf(rb1.y, s, sh));
            rb1.z = fmaxf(0.f, fmaf(rb1.z, s, sh)); rb1.w = fmaxf(0.f, fmaf(rb1.w, s, sh));
        }
#pragma unroll
        for (int kk = 0; kk < 16; kk++) {
            float4 a0 = *(float4*)&As[kk][ty * 8];
            float4 a1 = *(float4*)&As[kk][ty * 8 + 4];
            float4 b0 = *(float4*)&Bs[kk][tx * 8];
            float4 b1 = *(float4*)&Bs[kk][tx * 8 + 4];
            float a[8] = {a0.x, a0.y, a0.z, a0.w, a1.x, a1.y, a1.z, a1.w};
            float bb[8] = {b0.x, b0.y, b0.z, b0.w, b1.x, b1.y, b1.z, b1.w};
#pragma unroll
            for (int i = 0; i < 8; i++)
#pragma unroll
                for (int j = 0; j < 8; j++) acc[i][j] = fmaf(a[i], bb[j], acc[i][j]);
        }
        __syncthreads();
        if (has) {
            As[acol + 0][arow] = ra0.x; As[acol + 1][arow] = ra0.y;
            As[acol + 2][arow] = ra0.z; As[acol + 3][arow] = ra0.w;
            As[acol + 4][arow] = ra1.x; As[acol + 5][arow] = ra1.y;
            As[acol + 6][arow] = ra1.z; As[acol + 7][arow] = ra1.w;
            *(float4*)&Bs[brow][bcol] = rb0;
            *(float4*)&Bs[brow][bcol + 4] = rb1;
            __syncthreads();
        }
    }

    float* cp = Cm + (size_t)b * M * N + (size_t)(m0 + ty * 8) * N + n0 + tx * 8;
#pragma unroll
    for (int i = 0; i < 8; i++) {
        *(float4*)(cp + (size_t)i * N) = make_float4(acc[i][0], acc[i][1], acc[i][2], acc[i][3]);
        *(float4*)(cp + (size_t)i * N + 4) = make_float4(acc[i][4], acc[i][5], acc[i][6], acc[i][7]);
    }
#pragma unroll
    for (int i = 0; i < 8; i++) {
        float s = 0.f, sq = 0.f;
#pragma unroll
        for (int j = 0; j < 8; j++) { float v = acc[i][j]; s += v; sq += v * v; }
#pragma unroll
        for (int off = 1; off < 16; off <<= 1) {
            s += __shfl_xor_sync(0xffffffffu, s, off);
            sq += __shfl_xor_sync(0xffffffffu, sq, off);
        }
        if (tx == 0) {
            int c = m0 + ty * 8 + i;
            int part = b * gridDim.x + blockIdx.x;
            psum[(size_t)c * nparts + part] = s;
            psq[(size_t)c * nparts + part] = sq;
        }
    }
}

// ---- bf16 tensor-core GEMM: BM=128 BN=128 BK=32, 4-slot ring, prefetch depth 2, 1 sync/iter ----
// MODE_EPI: 1 = bnrelu+split store; 3 = partials+arg; 4 = partials no arg.
#define BG_STAGE_ELEMS 18944   // A 2x5120 + B 2x4352
template <int MODE_EPI>
__global__ __launch_bounds__(256)
void bgemm3(const __nv_bfloat16* __restrict__ Ahg, const __nv_bfloat16* __restrict__ Alg,
            const __nv_bfloat16* __restrict__ Bhg, const __nv_bfloat16* __restrict__ Blg,
            __nv_bfloat16* __restrict__ Ch, __nv_bfloat16* __restrict__ Cl,
            int M, int K, int N,
            const float* __restrict__ osc, const float* __restrict__ osh,
            float* __restrict__ psum, float* __restrict__ psq,
            float* __restrict__ pmax, int* __restrict__ pamax,
            float* __restrict__ pmin, int* __restrict__ pamin,
            int nparts)
{
    extern __shared__ __nv_bfloat16 smb[];
    int t = threadIdx.x;
    int b = blockIdx.z;
    int m0 = blockIdx.y * 128, n0 = blockIdx.x * 128;
    int lane = t & 31, wid = t >> 5;
    int warpM = wid & 3, warpN = wid >> 2;
    int grp = lane >> 2, qt = lane & 3;
    const __nv_bfloat16* Bhb = Bhg + (size_t)b * K * N;
    const __nv_bfloat16* Blb = Blg + (size_t)b * K * N;

    int arowL = t & 127, acp = (t >> 7) * 16;
    int browL = t >> 3, bcolL = (t & 7) * 16;

    float acc[2][8][4];
#pragma unroll
    for (int i = 0; i < 2; i++)
#pragma unroll
        for (int j = 0; j < 8; j++)
#pragma unroll
            for (int e = 0; e < 4; e++) acc[i][j][e] = 0.f;

#define PA(st, hl) (smb + (st) * BG_STAGE_ELEMS + (hl) * 5120)
#define PB(st, hl) (smb + (st) * BG_STAGE_ELEMS + 10240 + (hl) * 4352)

    auto load_stage = [&](int st, int k0) {
        cpasync16(PA(st, 0) + arowL * 40 + acp,     Ahg + (size_t)(m0 + arowL) * K + k0 + acp);
        cpasync16(PA(st, 0) + arowL * 40 + acp + 8, Ahg + (size_t)(m0 + arowL) * K + k0 + acp + 8);
        cpasync16(PA(st, 1) + arowL * 40 + acp,     Alg + (size_t)(m0 + arowL) * K + k0 + acp);
        cpasync16(PA(st, 1) + arowL * 40 + acp + 8, Alg + (size_t)(m0 + arowL) * K + k0 + acp + 8);
        cpasync16(PB(st, 0) + browL * 136 + bcolL,     Bhb + (size_t)(k0 + browL) * N + n0 + bcolL);
        cpasync16(PB(st, 0) + browL * 136 + bcolL + 8, Bhb + (size_t)(k0 + browL) * N + n0 + bcolL + 8);
        cpasync16(PB(st, 1) + browL * 136 + bcolL,     Blb + (size_t)(k0 + browL) * N + n0 + bcolL);
        cpasync16(PB(st, 1) + browL * 136 + bcolL + 8, Blb + (size_t)(k0 + browL) * N + n0 + bcolL + 8);
    };

    int nk = K >> 5;   // 4 for layer3/crit, 32 for Wc
    load_stage(0, 0);
    cp_commit();
    load_stage(1, 32);
    cp_commit();

    for (int kt = 0; kt < nk; kt++) {
        int cur = kt & 3;
        // prefetch depth 2: write target (kt+2)&3 == (kt-2)&3, read 2 iters ago.
        // skew < 1 iter (one barrier/iter) => laggards touch (kt-1)&3 / (kt+1)&3 only.
        if (kt + 2 < nk) load_stage((kt + 2) & 3, (kt + 2) << 5);
        cp_commit();          // uniform group count (empty group past the end)
        cp_wait<2>();         // group kt complete (2 prologue commits + 1/iter)
        __syncthreads();

#pragma unroll
        for (int ks = 0; ks < 2; ks++) {
            int kk = ks * 16;
            uint32_t ah[2][4], al[2][4];
#pragma unroll
            for (int i = 0; i < 2; i++) {
                int mr = warpM * 32 + i * 16 + (lane & 15);
                int mc = kk + (lane >> 4) * 8;
                ldsm_x4(ah[i], smem_u32(PA(cur, 0) + mr * 40 + mc));
                ldsm_x4(al[i], smem_u32(PA(cur, 1) + mr * 40 + mc));
            }
            uint32_t bh[8][2], bl[8][2];
#pragma unroll
            for (int p = 0; p < 4; p++) {
                int kr = kk + (lane & 15);
                int nc = warpN * 64 + p * 16 + (lane >> 4) * 8;
                uint32_t r[4];
                ldsm_x4_t(r, smem_u32(PB(cur, 0) + kr * 136 + nc));
                bh[p * 2][0] = r[0]; bh[p * 2][1] = r[1];
                bh[p * 2 + 1][0] = r[2]; bh[p * 2 + 1][1] = r[3];
                ldsm_x4_t(r, smem_u32(PB(cur, 1) + kr * 136 + nc));
                bl[p * 2][0] = r[0]; bl[p * 2][1] = r[1];
                bl[p * 2 + 1][0] = r[2]; bl[p * 2 + 1][1] = r[3];
            }
#pragma unroll
            for (int i = 0; i < 2; i++)
#pragma unroll
                for (int j = 0; j < 8; j++) {
                    mma_bf16(acc[i][j], ah[i], bh[j]);
                    mma_bf16(acc[i][j], ah[i], bl[j]);
                    mma_bf16(acc[i][j], al[i], bh[j]);
                }
        }
    }
    __syncthreads();   // all warps done with smem before epilogue aliasing

    if (MODE_EPI == 1) {
#pragma unroll
        for (int i = 0; i < 2; i++)
#pragma unroll
            for (int half = 0; half < 2; half++) {
                int c = m0 + warpM * 32 + i * 16 + grp + half * 8;
                float s = osc[c], sh = osh[c];
#pragma unroll
                for (int j = 0; j < 8; j++) {
                    float v0 = fmaxf(0.f, fmaf(acc[i][j][half * 2], s, sh));
                    float v1 = fmaxf(0.f, fmaf(acc[i][j][half * 2 + 1], s, sh));
                    __nv_bfloat16 h0, l0, h1, l1;
                    split_bf(v0, h0, l0);
                    split_bf(v1, h1, l1);
                    int n = n0 + warpN * 64 + j * 8 + qt * 2;
                    size_t idx = (size_t)b * M * N + (size_t)c * N + n;
                    __nv_bfloat162 ph; ph.x = h0; ph.y = h1;
                    __nv_bfloat162 pl; pl.x = l0; pl.y = l1;
                    *(__nv_bfloat162*)&Ch[idx] = ph;
                    *(__nv_bfloat162*)&Cl[idx] = pl;
                }
            }
    } else {
        float* eS  = (float*)smb;
        float* eQ  = eS + 256;
        float* eMx = eQ + 256;
        float* eMn = eMx + 256;
        int*   eAx = (int*)(eMn + 256);
        int*   eAn = eAx + 256;
#pragma unroll
        for (int i = 0; i < 2; i++)
#pragma unroll
            for (int half = 0; half < 2; half++) {
                float s = 0.f, sq = 0.f;
                float mx = -INFINITY, mn = INFINITY;
                int amx = 0, amn = 0;
#pragma unroll
                for (int j = 0; j < 8; j++)
#pragma unroll
                    for (int e = 0; e < 2; e++) {
                        float v = acc[i][j][half * 2 + e];
                        int n = n0 + warpN * 64 + j * 8 + qt * 2 + e;
                        s += v; sq += v * v;
                        if (v > mx) { mx = v; amx = n; }
                        if (v < mn) { mn = v; amn = n; }
                    }
#pragma unroll
                for (int off = 1; off < 4; off <<= 1) {
                    s += __shfl_xor_sync(0xffffffffu, s, off);
                    sq += __shfl_xor_sync(0xffffffffu, sq, off);
                    float ov = __shfl_xor_sync(0xffffffffu, mx, off);
                    int   oa = __shfl_xor_sync(0xffffffffu, amx, off);
                    if (ov > mx || (ov == mx && oa < amx)) { mx = ov; amx = oa; }
                    ov = __shfl_xor_sync(0xffffffffu, mn, off);
                    oa = __shfl_xor_sync(0xffffffffu, amn, off);
                    if (ov < mn || (ov == mn && oa < amn)) { mn = ov; amn = oa; }
                }
                if (qt == 0) {
                    int r = warpM * 32 + i * 16 + grp + half * 8;
                    eS[r * 2 + warpN] = s; eQ[r * 2 + warpN] = sq;
                    eMx[r * 2 + warpN] = mx; eMn[r * 2 + warpN] = mn;
                    eAx[r * 2 + warpN] = amx; eAn[r * 2 + warpN] = amn;
                }
            }
        __syncthreads();
        if (t < 128) {
            float s = eS[t * 2] + eS[t * 2 + 1];
            float sq = eQ[t * 2] + eQ[t * 2 + 1];
            float m0v = eMx[t * 2], m1v = eMx[t * 2 + 1];
            int a0 = eAx[t * 2], a1 = eAx[t * 2 + 1];
            float mx; int amx;
            if (m1v > m0v || (m1v == m0v && a1 < a0)) { mx = m1v; amx = a1; }
            else { mx = m0v; amx = a0; }
            float n0v = eMn[t * 2], n1v = eMn[t * 2 + 1];
            int b0 = eAn[t * 2], b1 = eAn[t * 2 + 1];
            float mn; int amn;
            if (n1v < n0v || (n1v == n0v && b1 < b0)) { mn = n1v; amn = b1; }
            else { mn = n0v; amn = b0; }
            int c = m0 + t;
            int part = b * gridDim.x + blockIdx.x;
            psum[(size_t)c * nparts + part] = s;
            psq[(size_t)c * nparts + part] = sq;
            size_t pi = ((size_t)((b << 10) + c)) * gridDim.x + blockIdx.x;
            pmax[pi] = mx; pmin[pi] = mn;
            if (MODE_EPI == 3) { pamax[pi] = amx; pamin[pi] = amn; }
        }
    }
#undef PA
#undef PB
}

// ---------------- CPL selection from partial max/min (8 tiles) ----------------
__global__ __launch_bounds__(256)
void cpl2_kernel(const float* __restrict__ pmax, const int* __restrict__ pamax,
                 const float* __restrict__ pmin, const int* __restrict__ pamin,
                 const float* __restrict__ sc3, const float* __restrict__ sh3,
                 int* __restrict__ outidx)
{
    __shared__ float s_val[1024];
    __shared__ int   s_aidx[1024];
    __shared__ float s_scores[1024];
    __shared__ float s_key[1024];
    __shared__ int   s_idx[1024];
    __shared__ int   s_packed[1024];
    __shared__ int   s_wsum[8];
    __shared__ int   s_m;

    int b = blockIdx.x;
    int t = threadIdx.x, lane = t & 31, warp = t >> 5;

    for (int c = t; c < 1024; c += 256) {
        float s3 = sc3[c], s3h = sh3[c];
        size_t base = ((size_t)((b << 10) + c)) * 8;
        float v; int a;
        if (s3 > 0.f) {
            v = pmax[base]; a = pamax[base];
#pragma unroll
            for (int nt = 1; nt < 8; nt++) {
                float ov = pmax[base + nt]; int oa = pamax[base + nt];
                if (ov > v || (ov == v && oa < a)) { v = ov; a = oa; }
            }
        } else {
            v = pmin[base]; a = pamin[base];
#pragma unroll
            for (int nt = 1; nt < 8; nt++) {
                float ov = pmin[base + nt]; int oa = pamin[base + nt];
                if (ov < v || (ov == v && oa < a)) { v = ov; a = oa; }
            }
        }
        s_val[c] = fmaxf(0.f, fmaf(v, s3, s3h));
        s_aidx[c] = a;
    }
    __syncthreads();

    float sc0 = 0.f, sc1 = 0.f, sc2 = 0.f, sc3q = 0.f;
    for (int c = 0; c < 1024; c++) {
        int ai = s_aidx[c];
        if ((ai & 255) == t) {
            float v = s_val[c];
            int q = ai >> 8;
            if (q == 0) sc0 += v; else if (q == 1) sc1 += v;
            else if (q == 2) sc2 += v; else sc3q += v;
        }
    }
    {
        float scq[4] = {sc0, sc1, sc2, sc3q};
#pragma unroll
        for (int q = 0; q < 4; q++) {
            int n = t + (q << 8);
            s_scores[n] = scq[q];
            s_key[n] = -scq[q] + CPL_EPS * (float)n;
            s_idx[n] = n;
        }
    }
    __syncthreads();

    for (int k = 2; k <= 1024; k <<= 1) {
        for (int j = k >> 1; j > 0; j >>= 1) {
#pragma unroll
            for (int base = t; base < 1024; base += 256) {
                int l = base ^ j;
                if (l > base) {
                    bool asc = ((base & k) == 0);
                    float k1 = s_key[base], k2 = s_key[l];
                    int i1 = s_idx[base], i2 = s_idx[l];
                    bool gt = (k1 > k2) || (k1 == k2 && i1 > i2);
                    if (gt == asc) {
                        s_key[base] = k2; s_key[l] = k1;
                        s_idx[base] = i2; s_idx[l] = i1;
                    }
                }
            }
            __syncthreads();
        }
    }

    int f0, f1, f2, f3, loc;
    int base4 = t * 4;
    f0 = (s_scores[s_idx[base4 + 0]] > 0.f) ? 1 : 0;
    f1 = (s_scores[s_idx[base4 + 1]] > 0.f) ? 1 : 0;
    f2 = (s_scores[s_idx[base4 + 2]] > 0.f) ? 1 : 0;
    f3 = (s_scores[s_idx[base4 + 3]] > 0.f) ? 1 : 0;
    loc = f0 + f1 + f2 + f3;
    int incl = loc;
#pragma unroll
    for (int off = 1; off < 32; off <<= 1) {
        int v = __shfl_up_sync(0xffffffffu, incl, off);
        if (lane >= off) incl += v;
    }
    if (lane == 31) s_wsum[warp] = incl;
    __syncthreads();
    if (t == 0) {
        int run = 0;
        for (int w = 0; w < 8; w++) { int v = s_wsum[w]; s_wsum[w] = run; run += v; }
        s_m = run;
    }
    __syncthreads();
    int m = s_m;
    int run = s_wsum[warp] + (incl - loc);
    {
        int fq[4] = {f0, f1, f2, f3};
#pragma unroll
        for (int q = 0; q < 4; q++) {
            int i = base4 + q;
            int pos = fq[q] ? run : (m + i - run);
            s_packed[pos] = s_idx[i];
            run += fq[q];
        }
    }
    __syncthreads();

    float m_eff = (m > 0) ? (float)m : (float)NPTS;
    int p;
    if (m_eff >= (float)KCPL) {
        p = t;
    } else {
        float lin = ((float)t * (m_eff - 1.0f)) / (float)(KCPL - 1);
        int pmaxv = (int)(m_eff - 1.0f);
        int r = (int)rintf(lin);
        p = min(max(r, 0), pmaxv);
    }
    outidx[b * KCPL + t] = s_packed[p];
}

// ---------------- gather split bn2relu(y2)[:, idx] -> h2g ----------------
__global__ void gather_kernel(const __nv_bfloat16* __restrict__ h3bh,
                              const __nv_bfloat16* __restrict__ h3bl,
                              const int* __restrict__ cidx,
                              __nv_bfloat16* __restrict__ h2gh, __nv_bfloat16* __restrict__ h2gl)
{
    int i = blockIdx.x * blockDim.x + threadIdx.x;
    if (i >= BATCH * 128 * KCPL) return;
    int j = i & 255;
    int k = (i >> 8) & 127;
    int b = i >> 15;
    int col = cidx[(b << 8) + j];
    size_t src = (((size_t)(b * 128 + k)) << 10) + col;
    h2gh[i] = h3bh[src];
    h2gl[i] = h3bl[src];
}

// ---------------- gfeat from Wc partial max/min (2 tiles) ----------------
__global__ void gfeat_kernel(const float* __restrict__ pmax, const float* __restrict__ pmin,
                             const float* __restrict__ scale, const float* __restrict__ shift,
                             float* __restrict__ gfeat)
{
    int i = blockIdx.x * 256 + threadIdx.x;
    if (i >= BATCH * 1024) return;
    int c = i & 1023;
    float s = scale[c], sh = shift[c];
    size_t base = (size_t)i * 2;
    float v;
    if (s > 0.f) v = fmaxf(pmax[base], pmax[base + 1]);
    else         v = fminf(pmin[base], pmin[base + 1]);
    gfeat[i] = fmaxf(0.f, fmaf(v, s, sh));
}

// ---------------- FC + batch-axis BN + relu (256 threads: 4 per batch) ----------------
__global__ __launch_bounds__(256)
void fc_bn_relu_kernel(const float* __restrict__ in,
                       const float* __restrict__ W,
                       const float* __restrict__ bias,
                       const float* __restrict__ g,
                       const float* __restrict__ bb,
                       float* __restrict__ out, int Cin)
{
    int c = blockIdx.x;
    int t = threadIdx.x;
    int b = t & 63, q = t >> 6;
    int Cout = gridDim.x;
    int chunk = Cin >> 2;
    const float* w = W + (size_t)c * Cin + q * chunk;
    const float* xb = in + (size_t)b * Cin + q * chunk;
    float acc = 0.f;
    for (int j = 0; j < chunk; j++) acc = fmaf(xb[j], w[j], acc);
    __shared__ float part[4][64];
    __shared__ float sy[64];
    __shared__ float s_scale, s_shift;
    part[q][b] = acc;
    __syncthreads();
    if (t < 64) {
        float a = part[0][t] + part[1][t] + part[2][t] + part[3][t] + bias[c];
        sy[t] = a;
    }
    __syncthreads();
    if (t == 0) {
        double s = 0.0, sq = 0.0;
        for (int i = 0; i < 64; i++) { s += sy[i]; sq += (double)sy[i] * sy[i]; }
        double mean = s / 64.0;
        double var = sq / 64.0 - mean * mean;
        float rs = rsqrtf((float)var + BN_EPS);
        float scl = g[c] * rs;
        s_scale = scl;
        s_shift = bb[c] - (float)mean * scl;
    }
    __syncthreads();
    if (t < 64)
        out[(size_t)t * Cout + c] = fmaxf(0.f, fmaf(sy[t], s_scale, s_shift));
}

// ---------------- final FC ----------------
__global__ void fc3_kernel(const float* __restrict__ in, const float* __restrict__ W,
                           const float* __restrict__ bias, float* __restrict__ out)
{
    int i = blockIdx.x * blockDim.x + threadIdx.x;
    if (i >= BATCH * NCLS) return;
    int b = i / NCLS, j = i - b * NCLS;
    float acc = bias[j];
    const float* xb = in + (size_t)b * 256;
    const float* w = W + (size_t)j * 256;
    for (int t = 0; t < 256; t++) acc = fmaf(xb[t], w[t], acc);
    out[i] = acc;
}

// ---------------- launch ----------------
extern "C" void kernel_launch(void* const* d_in, const int* in_sizes, int n_in,
                              void* d_out, int out_size)
{
    const float* x     = (const float*)d_in[0];
    const float* W1    = (const float*)d_in[1];
    const float* g1    = (const float*)d_in[2];
    const float* b1    = (const float*)d_in[3];
    const float* W2    = (const float*)d_in[4];
    const float* g2    = (const float*)d_in[5];
    const float* b2    = (const float*)d_in[6];
    const float* W3    = (const float*)d_in[7];
    const float* g3    = (const float*)d_in[8];
    const float* b3    = (const float*)d_in[9];
    const float* Wc    = (const float*)d_in[10];
    const float* gc    = (const float*)d_in[11];
    const float* bc    = (const float*)d_in[12];
    const float* fc1_w = (const float*)d_in[13];
    const float* fc1_b = (const float*)d_in[14];
    const float* bn1_g = (const float*)d_in[15];
    const float* bn1_b = (const float*)d_in[16];
    const float* fc2_w = (const float*)d_in[17];
    const float* fc2_b = (const float*)d_in[18];
    const float* bn2_g = (const float*)d_in[19];
    const float* bn2_b = (const float*)d_in[20];
    const float* fc3_w = (const float*)d_in[21];
    const float* fc3_b = (const float*)d_in[22];
    float* out = (float*)d_out;

    float *p_y1, *p_y2, *p_gfeat, *p_fc1h, *p_fc2h, *p_bn;
    float *p_psum3, *p_psq3, *p_pmax, *p_pmin, *p_psumc, *p_psqc;
    int *p_cidx, *p_pamax, *p_pamin;
    __nv_bfloat16 *p_h3bh, *p_h3bl, *p_h2gh, *p_h2gl, *p_crith, *p_critl;
    __nv_bfloat16 *p_W3h, *p_W3l, *p_Wch, *p_Wcl;
    cudaGetSymbolAddress((void**)&p_y1, g_y1);
    cudaGetSymbolAddress((void**)&p_y2, g_y2);
    cudaGetSymbolAddress((void**)&p_h3bh, g_h3bh);
    cudaGetSymbolAddress((void**)&p_h3bl, g_h3bl);
    cudaGetSymbolAddress((void**)&p_h2gh, g_h2gh);
    cudaGetSymbolAddress((void**)&p_h2gl, g_h2gl);
    cudaGetSymbolAddress((void**)&p_crith, g_crith);
    cudaGetSymbolAddress((void**)&p_critl, g_critl);
    cudaGetSymbolAddress((void**)&p_W3h, g_W3h);
    cudaGetSymbolAddress((void**)&p_W3l, g_W3l);
    cudaGetSymbolAddress((void**)&p_Wch, g_Wch);
    cudaGetSymbolAddress((void**)&p_Wcl, g_Wcl);
    cudaGetSymbolAddress((void**)&p_gfeat, g_gfeat);
    cudaGetSymbolAddress((void**)&p_fc1h, g_fc1h);
    cudaGetSymbolAddress((void**)&p_fc2h, g_fc2h);
    cudaGetSymbolAddress((void**)&p_bn, g_bn);
    cudaGetSymbolAddress((void**)&p_psum3, g_psum3);
    cudaGetSymbolAddress((void**)&p_psq3, g_psq3);
    cudaGetSymbolAddress((void**)&p_pmax, g_pmax);
    cudaGetSymbolAddress((void**)&p_pamax, g_pamax);
    cudaGetSymbolAddress((void**)&p_pmin, g_pmin);
    cudaGetSymbolAddress((void**)&p_pamin, g_pamin);
    cudaGetSymbolAddress((void**)&p_psumc, g_psumc);
    cudaGetSymbolAddress((void**)&p_psqc, g_psqc);
    cudaGetSymbolAddress((void**)&p_cidx, g_cidx);

    const int BG_SMEM = 4 * BG_STAGE_ELEMS * 2;   // 151552 bytes (4-slot ring)
    cudaFuncSetAttribute(bgemm3<1>, cudaFuncAttributeMaxDynamicSharedMemorySize, BG_SMEM);
    cudaFuncSetAttribute(bgemm3<3>, cudaFuncAttributeMaxDynamicSharedMemorySize, BG_SMEM);
    cudaFuncSetAttribute(bgemm3<4>, cudaFuncAttributeMaxDynamicSharedMemorySize, BG_SMEM);

    float* s1  = p_bn + 0 * 1024;
    float* sh1 = p_bn + 1 * 1024;
    float* s2  = p_bn + 2 * 1024;
    float* sh2 = p_bn + 3 * 1024;
    float* s3  = p_bn + 4 * 1024;
    float* sh3 = p_bn + 5 * 1024;
    float* scc = p_bn + 6 * 1024;
    float* shc = p_bn + 7 * 1024;

    mm1_split_kernel<<<MM1_BLOCKS + 4608, 256>>>(x, W1, p_y1, p_psum3, p_psq3,
                                                 W3, Wc, p_W3h, p_W3l, p_Wch, p_Wcl);
    reduce_parts<<<64, 128>>>(p_psum3, p_psq3, 256, (float)(BATCH * NPTS), g1, b1, s1, sh1);
    sgemm_f<<<dim3(8, 1, 64), 256>>>(W2, p_y1, p_y2, 128, 64, NPTS,
                                     s1, sh1, p_psum3, p_psq3, 512);
    reduce_parts<<<128, 128>>>(p_psum3, p_psq3, 512, (float)(BATCH * NPTS), g2, b2, s2, sh2);
    bnrelu_split<<<BATCH * 128 * NPTS / 256, 256>>>(p_y2, s2, sh2, p_h3bh, p_h3bl);
    bgemm3<3><<<dim3(8, 8, 64), 256, BG_SMEM>>>(p_W3h, p_W3l, p_h3bh, p_h3bl,
                                                nullptr, nullptr, 1024, 128, 1024,
                                                nullptr, nullptr,
                                                p_psum3, p_psq3, p_pmax, p_pamax, p_pmin, p_pamin, 512);
    reduce_parts<<<1024, 128>>>(p_psum3, p_psq3, 512, (float)(BATCH * NPTS), g3, b3, s3, sh3);
    cpl2_kernel<<<BATCH, 256>>>(p_pmax, p_pamax, p_pmin, p_pamin, s3, sh3, p_cidx);
    gather_kernel<<<(BATCH * 128 * KCPL + 255) / 256, 256>>>(p_h3bh, p_h3bl, p_cidx, p_h2gh, p_h2gl);
    bgemm3<1><<<dim3(2, 8, 64), 256, BG_SMEM>>>(p_W3h, p_W3l, p_h2gh, p_h2gl,
                                                p_crith, p_critl, 1024, 128, KCPL,
                                                s3, sh3,
                                                nullptr, nullptr, nullptr, nullptr, nullptr, nullptr, 0);
    bgemm3<4><<<dim3(2, 8, 64), 256, BG_SMEM>>>(p_Wch, p_Wcl, p_crith, p_critl,
                                                nullptr, nullptr, 1024, 1024, KCPL,
                                                nullptr, nullptr,
                                                p_psumc, p_psqc, p_pmax, nullptr, p_pmin, nullptr, 128);
    reduce_parts<<<1024, 128>>>(p_psumc, p_psqc, 128, (float)(BATCH * KCPL), gc, bc, scc, shc);
    gfeat_kernel<<<(BATCH * 1024 + 255) / 256, 256>>>(p_pmax, p_pmin, scc, shc, p_gfeat);
    fc_bn_relu_kernel<<<512, 256>>>(p_gfeat, fc1_w, fc1_b, bn1_g, bn1_b, p_fc1h, 1024);
    fc_bn_relu_kernel<<<256, 256>>>(p_fc1h, fc2_w, fc2_b, bn2_g, bn2_b, p_fc2h, 512);
    fc3_kernel<<<(BATCH * NCLS + 255) / 256, 256>>>(p_fc2h, fc3_w, fc3_b, out);
}

// round 16
// speedup vs baseline: 1.0451x; 1.0102x over previous
#include <cuda_runtime.h>
#include <cuda_bf16.h>
#include <math.h>
#include <stdint.h>

// ---------------- problem constants ----------------
#define BATCH 64
#define NPTS  1024
#define KCPL  256
#define NCLS  40
#define BN_EPS 1e-5f
#define CPL_EPS 1e-7f

// ---------------- device scratch ----------------
__device__ float g_y1[BATCH * 64 * NPTS];
__device__ float g_y2[BATCH * 128 * NPTS];
__device__ __nv_bfloat16 g_h1bh[BATCH * 64 * NPTS];
__device__ __nv_bfloat16 g_h1bl[BATCH * 64 * NPTS];
__device__ __nv_bfloat16 g_h3bh[BATCH * 128 * NPTS];
__device__ __nv_bfloat16 g_h3bl[BATCH * 128 * NPTS];
__device__ __nv_bfloat16 g_h2gh[BATCH * 128 * KCPL];
__device__ __nv_bfloat16 g_h2gl[BATCH * 128 * KCPL];
__device__ __nv_bfloat16 g_crith[(size_t)BATCH * 1024 * KCPL];
__device__ __nv_bfloat16 g_critl[(size_t)BATCH * 1024 * KCPL];
__device__ __nv_bfloat16 g_W2h[128 * 64], g_W2l[128 * 64];
__device__ __nv_bfloat16 g_W3h[1024 * 128], g_W3l[1024 * 128];
__device__ __nv_bfloat16 g_Wch[1024 * 1024], g_Wcl[1024 * 1024];
__device__ float g_psum3[1024 * 1024];
__device__ float g_psq3[1024 * 1024];
__device__ float g_pmax[BATCH * 1024 * 16];
__device__ int   g_pamax[BATCH * 1024 * 16];
__device__ float g_pmin[BATCH * 1024 * 16];
__device__ int   g_pamin[BATCH * 1024 * 16];
__device__ float g_psumc[1024 * 256];
__device__ float g_psqc[1024 * 256];
__device__ float g_gfeat[BATCH * 1024];
__device__ float g_fc1h[BATCH * 512];
__device__ float g_fc2h[BATCH * 256];
__device__ int   g_cidx[BATCH * KCPL];
__device__ float g_bn[8 * 1024];

// ---------------- ptx helpers ----------------
__device__ __forceinline__ uint32_t smem_u32(const void* p) {
    return (uint32_t)__cvta_generic_to_shared(p);
}
__device__ __forceinline__ void ldsm_x4(uint32_t* r, uint32_t a) {
    asm volatile("ldmatrix.sync.aligned.m8n8.x4.shared.b16 {%0,%1,%2,%3}, [%4];"
        : "=r"(r[0]), "=r"(r[1]), "=r"(r[2]), "=r"(r[3]) : "r"(a));
}
__device__ __forceinline__ void ldsm_x4_t(uint32_t* r, uint32_t a) {
    asm volatile("ldmatrix.sync.aligned.m8n8.x4.trans.shared.b16 {%0,%1,%2,%3}, [%4];"
        : "=r"(r[0]), "=r"(r[1]), "=r"(r[2]), "=r"(r[3]) : "r"(a));
}
__device__ __forceinline__ void mma_bf16(float* c, const uint32_t* a, const uint32_t* b2) {
    asm volatile("mma.sync.aligned.m16n8k16.row.col.f32.bf16.bf16.f32 "
        "{%0,%1,%2,%3}, {%4,%5,%6,%7}, {%8,%9}, {%0,%1,%2,%3};"
        : "+f"(c[0]), "+f"(c[1]), "+f"(c[2]), "+f"(c[3])
        : "r"(a[0]), "r"(a[1]), "r"(a[2]), "r"(a[3]), "r"(b2[0]), "r"(b2[1]));
}
__device__ __forceinline__ void split_bf(float x, __nv_bfloat16& h, __nv_bfloat16& l) {
    h = __float2bfloat16(x);
    l = __float2bfloat16(x - __bfloat162float(h));
}
__device__ __forceinline__ void cpasync16(void* s, const void* g) {
    asm volatile("cp.async.ca.shared.global [%0], [%1], 16;"
        :: "r"(smem_u32(s)), "l"(g));
}
__device__ __forceinline__ void cp_commit() { asm volatile("cp.async.commit_group;"); }
template <int W>
__device__ __forceinline__ void cp_wait() { asm volatile("cp.async.wait_group %0;" :: "n"(W)); }

// ---------------- fused: layer1 (3->64, partial stats) + weight splits ----------------
#define MM1_BLOCKS 16384
#define WSPLIT_ELEMS (1024 * 128 + 1024 * 1024 + 128 * 64)
__global__ void mm1_split_kernel(const float* __restrict__ x, const float* __restrict__ W1,
                                 float* __restrict__ y1,
                                 float* __restrict__ psum, float* __restrict__ psq,
                                 const float* __restrict__ W3, const float* __restrict__ Wc,
                                 const float* __restrict__ W2,
                                 __nv_bfloat16* __restrict__ W3h, __nv_bfloat16* __restrict__ W3l,
                                 __nv_bfloat16* __restrict__ Wch, __nv_bfloat16* __restrict__ Wcl,
                                 __nv_bfloat16* __restrict__ W2h, __nv_bfloat16* __restrict__ W2l)
{
    if (blockIdx.x >= MM1_BLOCKS) {
        int idx = (blockIdx.x - MM1_BLOCKS) * 256 + threadIdx.x;
        if (idx < 1024 * 128) {
            __nv_bfloat16 h, l;
            split_bf(W3[idx], h, l);
            W3h[idx] = h; W3l[idx] = l;
        } else {
            int j = idx - 1024 * 128;
            if (j < 1024 * 1024) {
                __nv_bfloat16 h, l;
                split_bf(Wc[j], h, l);
                Wch[j] = h; Wcl[j] = l;
            } else {
                int k = j - 1024 * 1024;
                if (k < 128 * 64) {
                    __nv_bfloat16 h, l;
                    split_bf(W2[k], h, l);
                    W2h[k] = h; W2l[k] = l;
                }
            }
        }
        return;
    }
    int i = blockIdx.x * 256 + threadIdx.x;
    int n = i & 1023;
    int c = (i >> 10) & 63;
    int b = i >> 16;
    const float* xp = x + ((size_t)(b << 10) + n) * 3;
    const float* w = W1 + c * 3;
    float v = w[0] * xp[0] + w[1] * xp[1] + w[2] * xp[2];
    y1[i] = v;

    float s = v, sq = v * v;
    int lane = threadIdx.x & 31, warp = threadIdx.x >> 5;
#pragma unroll
    for (int off = 16; off; off >>= 1) {
        s += __shfl_xor_sync(0xffffffffu, s, off);
        sq += __shfl_xor_sync(0xffffffffu, sq, off);
    }
    __shared__ float ws[8], wq[8];
    if (lane == 0) { ws[warp] = s; wq[warp] = sq; }
    __syncthreads();
    if (threadIdx.x == 0) {
        float ts = 0.f, tq = 0.f;
#pragma unroll
        for (int w8 = 0; w8 < 8; w8++) { ts += ws[w8]; tq += wq[w8]; }
        int part = b * 4 + (blockIdx.x & 3);
        psum[c * 256 + part] = ts;
        psq[c * 256 + part] = tq;
    }
}

// ---------------- bnrelu(y) -> bf16 hi/lo split (generic channel count) ----------------
__global__ void bnrelu_splitN(const float* __restrict__ y,
                              const float* __restrict__ sc, const float* __restrict__ sh,
                              __nv_bfloat16* __restrict__ oh, __nv_bfloat16* __restrict__ ol,
                              int cmask, int total)
{
    int i = blockIdx.x * 256 + threadIdx.x;
    if (i >= total) return;
    int c = (i >> 10) & cmask;
    float r = fmaxf(0.f, fmaf(y[i], sc[c], sh[c]));
    __nv_bfloat16 h, l;
    split_bf(r, h, l);
    oh[i] = h; ol[i] = l;
}

// ---------------- reduce partial stats -> scale/shift ----------------
__global__ void reduce_parts(const float* __restrict__ psum, const float* __restrict__ psq,
                             int nparts, float countf,
                             const float* __restrict__ g, const float* __restrict__ bt,
                             float* __restrict__ scale, float* __restrict__ shift)
{
    int c = blockIdx.x;
    int t = threadIdx.x;
    double s = 0.0, sq = 0.0;
    for (int i = t; i < nparts; i += blockDim.x) {
        s += (double)psum[(size_t)c * nparts + i];
        sq += (double)psq[(size_t)c * nparts + i];
    }
    __shared__ double ss[128], ssq[128];
    ss[t] = s; ssq[t] = sq;
    __syncthreads();
    for (int off = 64; off; off >>= 1) {
        if (t < off) { ss[t] += ss[t + off]; ssq[t] += ssq[t + off]; }
        __syncthreads();
    }
    if (t == 0) {
        double count = (double)countf;
        double mean = ss[0] / count;
        double var = ssq[0] / count - mean * mean;
        float rs = rsqrtf((float)var + BN_EPS);
        float sc = g[c] * rs;
        scale[c] = sc;
        shift[c] = bt[c] - (float)mean * sc;
    }
}

// ---------------- Wc stats reduce + fused gfeat (2 n-tiles) ----------------
__global__ void reduce_gfeat(const float* __restrict__ psum, const float* __restrict__ psq,
                             int nparts, float countf,
                             const float* __restrict__ g, const float* __restrict__ bt,
                             float* __restrict__ scale, float* __restrict__ shift,
                             const float* __restrict__ pmax, const float* __restrict__ pmin,
                             float* __restrict__ gfeat)
{
    int c = blockIdx.x;
    int t = threadIdx.x;
    double s = 0.0, sq = 0.0;
    for (int i = t; i < nparts; i += blockDim.x) {
        s += (double)psum[(size_t)c * nparts + i];
        sq += (double)psq[(size_t)c * nparts + i];
    }
    __shared__ double ss[128], ssq[128];
    __shared__ float s_sc, s_sh;
    ss[t] = s; ssq[t] = sq;
    __syncthreads();
    for (int off = 64; off; off >>= 1) {
        if (t < off) { ss[t] += ss[t + off]; ssq[t] += ssq[t + off]; }
        __syncthreads();
    }
    if (t == 0) {
        double count = (double)countf;
        double mean = ss[0] / count;
        double var = ssq[0] / count - mean * mean;
        float rs = rsqrtf((float)var + BN_EPS);
        float sc = g[c] * rs;
        scale[c] = sc;
        shift[c] = bt[c] - (float)mean * sc;
        s_sc = sc; s_sh = bt[c] - (float)mean * sc;
    }
    __syncthreads();
    if (t < 64) {
        float sc = s_sc, sh = s_sh;
        size_t base = ((size_t)((t << 10) + c)) * 2;
        float v;
        if (sc > 0.f) v = fmaxf(pmax[base], pmax[base + 1]);
        else          v = fminf(pmin[base], pmin[base + 1]);
        gfeat[t * 1024 + c] = fmaxf(0.f, fmaf(v, sc, sh));
    }
}

// ---- bf16 tensor-core GEMM: BM=128 BN=128 BK=32, 4-slot ring, prefetch depth 2, 1 sync/iter ----
// MODE_EPI: 1 = bnrelu+split store; 2 = raw fp32 store + sum/sq partials;
//           3 = partials+arg; 4 = partials no arg.
#define BG_STAGE_ELEMS 18944   // A 2x5120 + B 2x4352
template <int MODE_EPI>
__global__ __launch_bounds__(256)
void bgemm3(const __nv_bfloat16* __restrict__ Ahg, const __nv_bfloat16* __restrict__ Alg,
            const __nv_bfloat16* __restrict__ Bhg, const __nv_bfloat16* __restrict__ Blg,
            __nv_bfloat16* __restrict__ Ch, __nv_bfloat16* __restrict__ Cl,
            float* __restrict__ Cf,
            int M, int K, int N,
            const float* __restrict__ osc, const float* __restrict__ osh,
            float* __restrict__ psum, float* __restrict__ psq,
            float* __restrict__ pmax, int* __restrict__ pamax,
            float* __restrict__ pmin, int* __restrict__ pamin,
            int nparts)
{
    extern __shared__ __nv_bfloat16 smb[];
    int t = threadIdx.x;
    int b = blockIdx.z;
    int m0 = blockIdx.y * 128, n0 = blockIdx.x * 128;
    int lane = t & 31, wid = t >> 5;
    int warpM = wid & 3, warpN = wid >> 2;
    int grp = lane >> 2, qt = lane & 3;
    const __nv_bfloat16* Bhb = Bhg + (size_t)b * K * N;
    const __nv_bfloat16* Blb = Blg + (size_t)b * K * N;

    int arowL = t & 127, acp = (t >> 7) * 16;
    int browL = t >> 3, bcolL = (t & 7) * 16;

    float acc[2][8][4];
#pragma unroll
    for (int i = 0; i < 2; i++)
#pragma unroll
        for (int j = 0; j < 8; j++)
#pragma unroll
            for (int e = 0; e < 4; e++) acc[i][j][e] = 0.f;

#define PA(st, hl) (smb + (st) * BG_STAGE_ELEMS + (hl) * 5120)
#define PB(st, hl) (smb + (st) * BG_STAGE_ELEMS + 10240 + (hl) * 4352)

    auto load_stage = [&](int st, int k0) {
        cpasync16(PA(st, 0) + arowL * 40 + acp,     Ahg + (size_t)(m0 + arowL) * K + k0 + acp);
        cpasync16(PA(st, 0) + arowL * 40 + acp + 8, Ahg + (size_t)(m0 + arowL) * K + k0 + acp + 8);
        cpasync16(PA(st, 1) + arowL * 40 + acp,     Alg + (size_t)(m0 + arowL) * K + k0 + acp);
        cpasync16(PA(st, 1) + arowL * 40 + acp + 8, Alg + (size_t)(m0 + arowL) * K + k0 + acp + 8);
        cpasync16(PB(st, 0) + browL * 136 + bcolL,     Bhb + (size_t)(k0 + browL) * N + n0 + bcolL);
        cpasync16(PB(st, 0) + browL * 136 + bcolL + 8, Bhb + (size_t)(k0 + browL) * N + n0 + bcolL + 8);
        cpasync16(PB(st, 1) + browL * 136 + bcolL,     Blb + (size_t)(k0 + browL) * N + n0 + bcolL);
        cpasync16(PB(st, 1) + browL * 136 + bcolL + 8, Blb + (size_t)(k0 + browL) * N + n0 + bcolL + 8);
    };

    int nk = K >> 5;   // 2 layer2, 4 layer3/crit, 32 Wc
    load_stage(0, 0);
    cp_commit();
    load_stage(1, 32);
    cp_commit();

    for (int kt = 0; kt < nk; kt++) {
        int cur = kt & 3;
        // prefetch depth 2: write target (kt+2)&3 == (kt-2)&3, read 2 iters ago.
        // skew < 1 iter (one barrier/iter) => laggards touch (kt-1)&3 / (kt+1)&3 only.
        if (kt + 2 < nk) load_stage((kt + 2) & 3, (kt + 2) << 5);
        cp_commit();          // uniform group count (empty group past the end)
        cp_wait<2>();         // group kt complete (2 prologue commits + 1/iter)
        __syncthreads();

#pragma unroll
        for (int ks = 0; ks < 2; ks++) {
            int kk = ks * 16;
            uint32_t ah[2][4], al[2][4];
#pragma unroll
            for (int i = 0; i < 2; i++) {
                int mr = warpM * 32 + i * 16 + (lane & 15);
                int mc = kk + (lane >> 4) * 8;
                ldsm_x4(ah[i], smem_u32(PA(cur, 0) + mr * 40 + mc));
                ldsm_x4(al[i], smem_u32(PA(cur, 1) + mr * 40 + mc));
            }
            uint32_t bh[8][2], bl[8][2];
#pragma unroll
            for (int p = 0; p < 4; p++) {
                int kr = kk + (lane & 15);
                int nc = warpN * 64 + p * 16 + (lane >> 4) * 8;
                uint32_t r[4];
                ldsm_x4_t(r, smem_u32(PB(cur, 0) + kr * 136 + nc));
                bh[p * 2][0] = r[0]; bh[p * 2][1] = r[1];
                bh[p * 2 + 1][0] = r[2]; bh[p * 2 + 1][1] = r[3];
                ldsm_x4_t(r, smem_u32(PB(cur, 1) + kr * 136 + nc));
                bl[p * 2][0] = r[0]; bl[p * 2][1] = r[1];
                bl[p * 2 + 1][0] = r[2]; bl[p * 2 + 1][1] = r[3];
            }
#pragma unroll
            for (int i = 0; i < 2; i++)
#pragma unroll
                for (int j = 0; j < 8; j++) {
                    mma_bf16(acc[i][j], ah[i], bh[j]);
                    mma_bf16(acc[i][j], ah[i], bl[j]);
                    mma_bf16(acc[i][j], al[i], bh[j]);
                }
        }
    }
    __syncthreads();   // all warps done with smem before epilogue aliasing

    if (MODE_EPI == 1) {
#pragma unroll
        for (int i = 0; i < 2; i++)
#pragma unroll
            for (int half = 0; half < 2; half++) {
                int c = m0 + warpM * 32 + i * 16 + grp + half * 8;
                float s = osc[c], sh = osh[c];
#pragma unroll
                for (int j = 0; j < 8; j++) {
                    float v0 = fmaxf(0.f, fmaf(acc[i][j][half * 2], s, sh));
                    float v1 = fmaxf(0.f, fmaf(acc[i][j][half * 2 + 1], s, sh));
                    __nv_bfloat16 h0, l0, h1, l1;
                    split_bf(v0, h0, l0);
                    split_bf(v1, h1, l1);
                    int n = n0 + warpN * 64 + j * 8 + qt * 2;
                    size_t idx = (size_t)b * M * N + (size_t)c * N + n;
                    __nv_bfloat162 ph; ph.x = h0; ph.y = h1;
                    __nv_bfloat162 pl; pl.x = l0; pl.y = l1;
                    *(__nv_bfloat162*)&Ch[idx] = ph;
                    *(__nv_bfloat162*)&Cl[idx] = pl;
                }
            }
    } else if (MODE_EPI == 2) {
        // raw fp32 store + sum/sq partials
        float* eS  = (float*)smb;
        float* eQ  = eS + 256;
#pragma unroll
        for (int i = 0; i < 2; i++)
#pragma unroll
            for (int half = 0; half < 2; half++) {
                int c = m0 + warpM * 32 + i * 16 + grp + half * 8;
                float s = 0.f, sq = 0.f;
#pragma unroll
                for (int j = 0; j < 8; j++) {
                    float v0 = acc[i][j][half * 2];
                    float v1 = acc[i][j][half * 2 + 1];
                    int n = n0 + warpN * 64 + j * 8 + qt * 2;
                    *(float2*)&Cf[(size_t)b * M * N + (size_t)c * N + n] = make_float2(v0, v1);
                    s += v0 + v1; sq += v0 * v0 + v1 * v1;
                }
#pragma unroll
                for (int off = 1; off < 4; off <<= 1) {
                    s += __shfl_xor_sync(0xffffffffu, s, off);
                    sq += __shfl_xor_sync(0xffffffffu, sq, off);
                }
                if (qt == 0) {
                    int r = warpM * 32 + i * 16 + grp + half * 8;
                    eS[r * 2 + warpN] = s; eQ[r * 2 + warpN] = sq;
                }
            }
        __syncthreads();
        if (t < 128) {
            float s = eS[t * 2] + eS[t * 2 + 1];
            float sq = eQ[t * 2] + eQ[t * 2 + 1];
            int c = m0 + t;
            int part = b * gridDim.x + blockIdx.x;
            psum[(size_t)c * nparts + part] = s;
            psq[(size_t)c * nparts + part] = sq;
        }
    } else {
        float* eS  = (float*)smb;
        float* eQ  = eS + 256;
        float* eMx = eQ + 256;
        float* eMn = eMx + 256;
        int*   eAx = (int*)(eMn + 256);
        int*   eAn = eAx + 256;
#pragma unroll
        for (int i = 0; i < 2; i++)
#pragma unroll
            for (int half = 0; half < 2; half++) {
                float s = 0.f, sq = 0.f;
                float mx = -INFINITY, mn = INFINITY;
                int amx = 0, amn = 0;
#pragma unroll
                for (int j = 0; j < 8; j++)
#pragma unroll
                    for (int e = 0; e < 2; e++) {
                        float v = acc[i][j][half * 2 + e];
                        int n = n0 + warpN * 64 + j * 8 + qt * 2 + e;
                        s += v; sq += v * v;
                        if (v > mx) { mx = v; amx = n; }
                        if (v < mn) { mn = v; amn = n; }
                    }
#pragma unroll
                for (int off = 1; off < 4; off <<= 1) {
                    s += __shfl_xor_sync(0xffffffffu, s, off);
                    sq += __shfl_xor_sync(0xffffffffu, sq, off);
                    float ov = __shfl_xor_sync(0xffffffffu, mx, off);
                    int   oa = __shfl_xor_sync(0xffffffffu, amx, off);
                    if (ov > mx || (ov == mx && oa < amx)) { mx = ov; amx = oa; }
                    ov = __shfl_xor_sync(0xffffffffu, mn, off);
                    oa = __shfl_xor_sync(0xffffffffu, amn, off);
                    if (ov < mn || (ov == mn && oa < amn)) { mn = ov; amn = oa; }
                }
                if (qt == 0) {
                    int r = warpM * 32 + i * 16 + grp + half * 8;
                    eS[r * 2 + warpN] = s; eQ[r * 2 + warpN] = sq;
                    eMx[r * 2 + warpN] = mx; eMn[r * 2 + warpN] = mn;
                    eAx[r * 2 + warpN] = amx; eAn[r * 2 + warpN] = amn;
                }
            }
        __syncthreads();
        if (t < 128) {
            float s = eS[t * 2] + eS[t * 2 + 1];
            float sq = eQ[t * 2] + eQ[t * 2 + 1];
            float m0v = eMx[t * 2], m1v = eMx[t * 2 + 1];
            int a0 = eAx[t * 2], a1 = eAx[t * 2 + 1];
            float mx; int amx;
            if (m1v > m0v || (m1v == m0v && a1 < a0)) { mx = m1v; amx = a1; }
            else { mx = m0v; amx = a0; }
            float n0v = eMn[t * 2], n1v = eMn[t * 2 + 1];
            int b0 = eAn[t * 2], b1 = eAn[t * 2 + 1];
            float mn; int amn;
            if (n1v < n0v || (n1v == n0v && b1 < b0)) { mn = n1v; amn = b1; }
            else { mn = n0v; amn = b0; }
            int c = m0 + t;
            int part = b * gridDim.x + blockIdx.x;
            psum[(size_t)c * nparts + part] = s;
            psq[(size_t)c * nparts + part] = sq;
            size_t pi = ((size_t)((b << 10) + c)) * gridDim.x + blockIdx.x;
            pmax[pi] = mx; pmin[pi] = mn;
            if (MODE_EPI == 3) { pamax[pi] = amx; pamin[pi] = amn; }
        }
    }
#undef PA
#undef PB
}

// ---------------- CPL selection from partial max/min (8 tiles) ----------------
__global__ __launch_bounds__(256)
void cpl2_kernel(const float* __restrict__ pmax, const int* __restrict__ pamax,
                 const float* __restrict__ pmin, const int* __restrict__ pamin,
                 const float* __restrict__ sc3, const float* __restrict__ sh3,
                 int* __restrict__ outidx)
{
    __shared__ float s_val[1024];
    __shared__ int   s_aidx[1024];
    __shared__ float s_scores[1024];
    __shared__ float s_key[1024];
    __shared__ int   s_idx[1024];
    __shared__ int   s_packed[1024];
    __shared__ int   s_wsum[8];
    __shared__ int   s_m;

    int b = blockIdx.x;
    int t = threadIdx.x, lane = t & 31, warp = t >> 5;

    for (int c = t; c < 1024; c += 256) {
        float s3 = sc3[c], s3h = sh3[c];
        size_t base = ((size_t)((b << 10) + c)) * 8;
        float v; int a;
        if (s3 > 0.f) {
            v = pmax[base]; a = pamax[base];
#pragma unroll
            for (int nt = 1; nt < 8; nt++) {
                float ov = pmax[base + nt]; int oa = pamax[base + nt];
                if (ov > v || (ov == v && oa < a)) { v = ov; a = oa; }
            }
        } else {
            v = pmin[base]; a = pamin[base];
#pragma unroll
            for (int nt = 1; nt < 8; nt++) {
                float ov = pmin[base + nt]; int oa = pamin[base + nt];
                if (ov < v || (ov == v && oa < a)) { v = ov; a = oa; }
            }
        }
        s_val[c] = fmaxf(0.f, fmaf(v, s3, s3h));
        s_aidx[c] = a;
    }
    __syncthreads();

    float sc0 = 0.f, sc1 = 0.f, sc2 = 0.f, sc3q = 0.f;
    for (int c = 0; c < 1024; c++) {
        int ai = s_aidx[c];
        if ((ai & 255) == t) {
            float v = s_val[c];
            int q = ai >> 8;
            if (q == 0) sc0 += v; else if (q == 1) sc1 += v;
            else if (q == 2) sc2 += v; else sc3q += v;
        }
    }
    {
        float scq[4] = {sc0, sc1, sc2, sc3q};
#pragma unroll
        for (int q = 0; q < 4; q++) {
            int n = t + (q << 8);
            s_scores[n] = scq[q];
            s_key[n] = -scq[q] + CPL_EPS * (float)n;
            s_idx[n] = n;
        }
    }
    __syncthreads();

    for (int k = 2; k <= 1024; k <<= 1) {
        for (int j = k >> 1; j > 0; j >>= 1) {
#pragma unroll
            for (int base = t; base < 1024; base += 256) {
                int l = base ^ j;
                if (l > base) {
                    bool asc = ((base & k) == 0);
                    float k1 = s_key[base], k2 = s_key[l];
                    int i1 = s_idx[base], i2 = s_idx[l];
                    bool gt = (k1 > k2) || (k1 == k2 && i1 > i2);
                    if (gt == asc) {
                        s_key[base] = k2; s_key[l] = k1;
                        s_idx[base] = i2; s_idx[l] = i1;
                    }
                }
            }
            __syncthreads();
        }
    }

    int f0, f1, f2, f3, loc;
    int base4 = t * 4;
    f0 = (s_scores[s_idx[base4 + 0]] > 0.f) ? 1 : 0;
    f1 = (s_scores[s_idx[base4 + 1]] > 0.f) ? 1 : 0;
    f2 = (s_scores[s_idx[base4 + 2]] > 0.f) ? 1 : 0;
    f3 = (s_scores[s_idx[base4 + 3]] > 0.f) ? 1 : 0;
    loc = f0 + f1 + f2 + f3;
    int incl = loc;
#pragma unroll
    for (int off = 1; off < 32; off <<= 1) {
        int v = __shfl_up_sync(0xffffffffu, incl, off);
        if (lane >= off) incl += v;
    }
    if (lane == 31) s_wsum[warp] = incl;
    __syncthreads();
    if (t == 0) {
        int run = 0;
        for (int w = 0; w < 8; w++) { int v = s_wsum[w]; s_wsum[w] = run; run += v; }
        s_m = run;
    }
    __syncthreads();
    int m = s_m;
    int run = s_wsum[warp] + (incl - loc);
    {
        int fq[4] = {f0, f1, f2, f3};
#pragma unroll
        for (int q = 0; q < 4; q++) {
            int i = base4 + q;
            int pos = fq[q] ? run : (m + i - run);
            s_packed[pos] = s_idx[i];
            run += fq[q];
        }
    }
    __syncthreads();

    float m_eff = (m > 0) ? (float)m : (float)NPTS;
    int p;
    if (m_eff >= (float)KCPL) {
        p = t;
    } else {
        float lin = ((float)t * (m_eff - 1.0f)) / (float)(KCPL - 1);
        int pmaxv = (int)(m_eff - 1.0f);
        int r = (int)rintf(lin);
        p = min(max(r, 0), pmaxv);
    }
    outidx[b * KCPL + t] = s_packed[p];
}

// ---------------- gather split bn2relu(y2)[:, idx] -> h2g ----------------
__global__ void gather_kernel(const __nv_bfloat16* __restrict__ h3bh,
                              const __nv_bfloat16* __restrict__ h3bl,
                              const int* __restrict__ cidx,
                              __nv_bfloat16* __restrict__ h2gh, __nv_bfloat16* __restrict__ h2gl)
{
    int i = blockIdx.x * blockDim.x + threadIdx.x;
    if (i >= BATCH * 128 * KCPL) return;
    int j = i & 255;
    int k = (i >> 8) & 127;
    int b = i >> 15;
    int col = cidx[(b << 8) + j];
    size_t src = (((size_t)(b * 128 + k)) << 10) + col;
    h2gh[i] = h3bh[src];
    h2gl[i] = h3bl[src];
}

// ---------------- FC + batch-axis BN + relu (256 threads: 4 per batch) ----------------
__global__ __launch_bounds__(256)
void fc_bn_relu_kernel(const float* __restrict__ in,
                       const float* __restrict__ W,
                       const float* __restrict__ bias,
                       const float* __restrict__ g,
                       const float* __restrict__ bb,
                       float* __restrict__ out, int Cin)
{
    int c = blockIdx.x;
    int t = threadIdx.x;
    int b = t & 63, q = t >> 6;
    int Cout = gridDim.x;
    int chunk = Cin >> 2;
    const float* w = W + (size_t)c * Cin + q * chunk;
    const float* xb = in + (size_t)b * Cin + q * chunk;
    float acc = 0.f;
    for (int j = 0; j < chunk; j++) acc = fmaf(xb[j], w[j], acc);
    __shared__ float part[4][64];
    __shared__ float sy[64];
    __shared__ float s_scale, s_shift;
    part[q][b] = acc;
    __syncthreads();
    if (t < 64) {
        float a = part[0][t] + part[1][t] + part[2][t] + part[3][t] + bias[c];
        sy[t] = a;
    }
    __syncthreads();
    if (t == 0) {
        double s = 0.0, sq = 0.0;
        for (int i = 0; i < 64; i++) { s += sy[i]; sq += (double)sy[i] * sy[i]; }
        double mean = s / 64.0;
        double var = sq / 64.0 - mean * mean;
        float rs = rsqrtf((float)var + BN_EPS);
        float scl = g[c] * rs;
        s_scale = scl;
        s_shift = bb[c] - (float)mean * scl;
    }
    __syncthreads();
    if (t < 64)
        out[(size_t)t * Cout + c] = fmaxf(0.f, fmaf(sy[t], s_scale, s_shift));
}

// ---------------- final FC ----------------
__global__ void fc3_kernel(const float* __restrict__ in, const float* __restrict__ W,
                           const float* __restrict__ bias, float* __restrict__ out)
{
    int i = blockIdx.x * blockDim.x + threadIdx.x;
    if (i >= BATCH * NCLS) return;
    int b = i / NCLS, j = i - b * NCLS;
    float acc = bias[j];
    const float* xb = in + (size_t)b * 256;
    const float* w = W + (size_t)j * 256;
    for (int t = 0; t < 256; t++) acc = fmaf(xb[t], w[t], acc);
    out[i] = acc;
}

// ---------------- launch ----------------
extern "C" void kernel_launch(void* const* d_in, const int* in_sizes, int n_in,
                              void* d_out, int out_size)
{
    const float* x     = (const float*)d_in[0];
    const float* W1    = (const float*)d_in[1];
    const float* g1    = (const float*)d_in[2];
    const float* b1    = (const float*)d_in[3];
    const float* W2    = (const float*)d_in[4];
    const float* g2    = (const float*)d_in[5];
    const float* b2    = (const float*)d_in[6];
    const float* W3    = (const float*)d_in[7];
    const float* g3    = (const float*)d_in[8];
    const float* b3    = (const float*)d_in[9];
    const float* Wc    = (const float*)d_in[10];
    const float* gc    = (const float*)d_in[11];
    const float* bc    = (const float*)d_in[12];
    const float* fc1_w = (const float*)d_in[13];
    const float* fc1_b = (const float*)d_in[14];
    const float* bn1_g = (const float*)d_in[15];
    const float* bn1_b = (const float*)d_in[16];
    const float* fc2_w = (const float*)d_in[17];
    const float* fc2_b = (const float*)d_in[18];
    const float* bn2_g = (const float*)d_in[19];
    const float* bn2_b = (const float*)d_in[20];
    const float* fc3_w = (const float*)d_in[21];
    const float* fc3_b = (const float*)d_in[22];
    float* out = (float*)d_out;

    float *p_y1, *p_y2, *p_gfeat, *p_fc1h, *p_fc2h, *p_bn;
    float *p_psum3, *p_psq3, *p_pmax, *p_pmin, *p_psumc, *p_psqc;
    int *p_cidx, *p_pamax, *p_pamin;
    __nv_bfloat16 *p_h1bh, *p_h1bl, *p_h3bh, *p_h3bl, *p_h2gh, *p_h2gl, *p_crith, *p_critl;
    __nv_bfloat16 *p_W2h, *p_W2l, *p_W3h, *p_W3l, *p_Wch, *p_Wcl;
    cudaGetSymbolAddress((void**)&p_y1, g_y1);
    cudaGetSymbolAddress((void**)&p_y2, g_y2);
    cudaGetSymbolAddress((void**)&p_h1bh, g_h1bh);
    cudaGetSymbolAddress((void**)&p_h1bl, g_h1bl);
    cudaGetSymbolAddress((void**)&p_h3bh, g_h3bh);
    cudaGetSymbolAddress((void**)&p_h3bl, g_h3bl);
    cudaGetSymbolAddress((void**)&p_h2gh, g_h2gh);
    cudaGetSymbolAddress((void**)&p_h2gl, g_h2gl);
    cudaGetSymbolAddress((void**)&p_crith, g_crith);
    cudaGetSymbolAddress((void**)&p_critl, g_critl);
    cudaGetSymbolAddress((void**)&p_W2h, g_W2h);
    cudaGetSymbolAddress((void**)&p_W2l, g_W2l);
    cudaGetSymbolAddress((void**)&p_W3h, g_W3h);
    cudaGetSymbolAddress((void**)&p_W3l, g_W3l);
    cudaGetSymbolAddress((void**)&p_Wch, g_Wch);
    cudaGetSymbolAddress((void**)&p_Wcl, g_Wcl);
    cudaGetSymbolAddress((void**)&p_gfeat, g_gfeat);
    cudaGetSymbolAddress((void**)&p_fc1h, g_fc1h);
    cudaGetSymbolAddress((void**)&p_fc2h, g_fc2h);
    cudaGetSymbolAddress((void**)&p_bn, g_bn);
    cudaGetSymbolAddress((void**)&p_psum3, g_psum3);
    cudaGetSymbolAddress((void**)&p_psq3, g_psq3);
    cudaGetSymbolAddress((void**)&p_pmax, g_pmax);
    cudaGetSymbolAddress((void**)&p_pamax, g_pamax);
    cudaGetSymbolAddress((void**)&p_pmin, g_pmin);
    cudaGetSymbolAddress((void**)&p_pamin, g_pamin);
    cudaGetSymbolAddress((void**)&p_psumc, g_psumc);
    cudaGetSymbolAddress((void**)&p_psqc, g_psqc);
    cudaGetSymbolAddress((void**)&p_cidx, g_cidx);

    const int BG_SMEM = 4 * BG_STAGE_ELEMS * 2;   // 151552 bytes (4-slot ring)
    cudaFuncSetAttribute(bgemm3<1>, cudaFuncAttributeMaxDynamicSharedMemorySize, BG_SMEM);
    cudaFuncSetAttribute(bgemm3<2>, cudaFuncAttributeMaxDynamicSharedMemorySize, BG_SMEM);
    cudaFuncSetAttribute(bgemm3<3>, cudaFuncAttributeMaxDynamicSharedMemorySize, BG_SMEM);
    cudaFuncSetAttribute(bgemm3<4>, cudaFuncAttributeMaxDynamicSharedMemorySize, BG_SMEM);

    float* s1  = p_bn + 0 * 1024;
    float* sh1 = p_bn + 1 * 1024;
    float* s2  = p_bn + 2 * 1024;
    float* sh2 = p_bn + 3 * 1024;
    float* s3  = p_bn + 4 * 1024;
    float* sh3 = p_bn + 5 * 1024;
    float* scc = p_bn + 6 * 1024;
    float* shc = p_bn + 7 * 1024;

    // 1: layer1 + weight splits (W3, Wc, W2)
    mm1_split_kernel<<<MM1_BLOCKS + (WSPLIT_ELEMS + 255) / 256, 256>>>(
        x, W1, p_y1, p_psum3, p_psq3, W3, Wc, W2,
        p_W3h, p_W3l, p_Wch, p_Wcl, p_W2h, p_W2l);
    // 2: bn1 stats
    reduce_parts<<<64, 128>>>(p_psum3, p_psq3, 256, (float)(BATCH * NPTS), g1, b1, s1, sh1);
    // 3: bn1relu(y1) -> bf16 split
    bnrelu_splitN<<<BATCH * 64 * NPTS / 256, 256>>>(p_y1, s1, sh1, p_h1bh, p_h1bl,
                                                    63, BATCH * 64 * NPTS);
    // 4: layer2 (tensor core, raw fp32 store + partials)
    bgemm3<2><<<dim3(8, 1, 64), 256, BG_SMEM>>>(p_W2h, p_W2l, p_h1bh, p_h1bl,
                                                nullptr, nullptr, p_y2, 128, 64, NPTS,
                                                nullptr, nullptr,
                                                p_psum3, p_psq3, nullptr, nullptr, nullptr, nullptr, 512);
    // 5: bn2 stats
    reduce_parts<<<128, 128>>>(p_psum3, p_psq3, 512, (float)(BATCH * NPTS), g2, b2, s2, sh2);
    // 6: bn2relu(y2) -> bf16 split
    bnrelu_splitN<<<BATCH * 128 * NPTS / 256, 256>>>(p_y2, s2, sh2, p_h3bh, p_h3bl,
                                                     127, BATCH * 128 * NPTS);
    // 7: layer3 (tensor core), NO store, partials + arg (8 n-tiles)
    bgemm3<3><<<dim3(8, 8, 64), 256, BG_SMEM>>>(p_W3h, p_W3l, p_h3bh, p_h3bl,
                                                nullptr, nullptr, nullptr, 1024, 128, 1024,
                                                nullptr, nullptr,
                                                p_psum3, p_psq3, p_pmax, p_pamax, p_pmin, p_pamin, 512);
    // 8: bn3 stats
    reduce_parts<<<1024, 128>>>(p_psum3, p_psq3, 512, (float)(BATCH * NPTS), g3, b3, s3, sh3);
    // 9: CPL selection
    cpl2_kernel<<<BATCH, 256>>>(p_pmax, p_pamax, p_pmin, p_pamin, s3, sh3, p_cidx);
    // 10: gather
    gather_kernel<<<(BATCH * 128 * KCPL + 255) / 256, 256>>>(p_h3bh, p_h3bl, p_cidx, p_h2gh, p_h2gl);
    // 11: crit features (bnrelu+split store)
    bgemm3<1><<<dim3(2, 8, 64), 256, BG_SMEM>>>(p_W3h, p_W3l, p_h2gh, p_h2gl,
                                                p_crith, p_critl, nullptr, 1024, 128, KCPL,
                                                s3, sh3,
                                                nullptr, nullptr, nullptr, nullptr, nullptr, nullptr, 0);
    // 12: Wc GEMM, NO store, partials (2 n-tiles)
    bgemm3<4><<<dim3(2, 8, 64), 256, BG_SMEM>>>(p_Wch, p_Wcl, p_crith, p_critl,
                                                nullptr, nullptr, nullptr, 1024, 1024, KCPL,
                                                nullptr, nullptr,
                                                p_psumc, p_psqc, p_pmax, nullptr, p_pmin, nullptr, 128);
    // 13: bnC stats + fused gfeat
    reduce_gfeat<<<1024, 128>>>(p_psumc, p_psqc, 128, (float)(BATCH * KCPL), gc, bc, scc, shc,
                                p_pmax, p_pmin, p_gfeat);
    // 14-16: classifier head
    fc_bn_relu_kernel<<<512, 256>>>(p_gfeat, fc1_w, fc1_b, bn1_g, bn1_b, p_fc1h, 1024);
    fc_bn_relu_kernel<<<256, 256>>>(p_fc1h, fc2_w, fc2_b, bn2_g, bn2_b, p_fc2h, 512);
    fc3_kernel<<<(BATCH * NCLS + 255) / 256, 256>>>(p_fc2h, fc3_w, fc3_b, out);
}